// round 1
// baseline (speedup 1.0000x reference)
#include <cuda_runtime.h>
#include <math.h>

// Problem constants
#define EDIM 1024
#define NTOK 4096          // B*T = 4*1024
#define FDIM 4096
#define NH   16
#define HD   64

// Scratch (allocation-free rule: __device__ globals)
__device__ float g_h  [NTOK * EDIM];          // 16 MB  (LN output, reused)
__device__ float g_qkv[NTOK * 3 * EDIM];      // 48 MB
__device__ float g_att[NTOK * EDIM];          // 16 MB
__device__ float g_x1 [NTOK * EDIM];          // 16 MB  (residual after attention)
__device__ float g_ff [(size_t)NTOK * FDIM];  // 64 MB

// ---------------------------------------------------------------------------
// LayerNorm: one block per row of 1024 floats, 256 threads (1 float4 each)
// ---------------------------------------------------------------------------
__global__ __launch_bounds__(256) void ln_kernel(
    const float* __restrict__ x, const float* __restrict__ w,
    const float* __restrict__ b, float* __restrict__ out)
{
    __shared__ float red[2][8];
    int row = blockIdx.x;
    int tid = threadIdx.x;
    const float4* xr = (const float4*)(x + (size_t)row * EDIM);
    float4 v = xr[tid];
    float s  = v.x + v.y + v.z + v.w;
    float ss = v.x*v.x + v.y*v.y + v.z*v.z + v.w*v.w;
    #pragma unroll
    for (int o = 16; o; o >>= 1) {
        s  += __shfl_xor_sync(0xffffffffu, s,  o);
        ss += __shfl_xor_sync(0xffffffffu, ss, o);
    }
    int wid = tid >> 5, lid = tid & 31;
    if (lid == 0) { red[0][wid] = s; red[1][wid] = ss; }
    __syncthreads();
    s = 0.f; ss = 0.f;
    #pragma unroll
    for (int i = 0; i < 8; i++) { s += red[0][i]; ss += red[1][i]; }
    float mu  = s * (1.0f / EDIM);
    float var = ss * (1.0f / EDIM) - mu * mu;
    float inv = rsqrtf(var + 1e-5f);
    float4 wv = ((const float4*)w)[tid];
    float4 bv = ((const float4*)b)[tid];
    float4 o;
    o.x = (v.x - mu) * inv * wv.x + bv.x;
    o.y = (v.y - mu) * inv * wv.y + bv.y;
    o.z = (v.z - mu) * inv * wv.z + bv.z;
    o.w = (v.w - mu) * inv * wv.w + bv.w;
    ((float4*)(out + (size_t)row * EDIM))[tid] = o;
}

// ---------------------------------------------------------------------------
// SGEMM  C[M,N] = A[M,K] @ Bw[N,K]^T  (both row-major, K contiguous -> "NT")
// 128x128x16 tile, 256 threads, 8x8 per thread (split 4+4 for conflict-free LDS)
// EPI: 0 = +bias, 1 = +bias+residual, 2 = +bias+exact GELU
// All M,N multiples of 128 and K multiples of 16 in this problem -> no guards.
// ---------------------------------------------------------------------------
template <int EPI>
__global__ __launch_bounds__(256) void gemm_nt(
    const float* __restrict__ A, const float* __restrict__ Bw,
    const float* __restrict__ bias, const float* __restrict__ R,
    float* __restrict__ C, int M, int N, int K)
{
    constexpr int BM = 128, BN = 128, BK = 16;
    __shared__ float As[BK][BM + 4];
    __shared__ float Bs[BK][BN + 4];

    int tid = threadIdx.x;
    int tx = tid & 15, ty = tid >> 4;
    int m0 = blockIdx.y * BM, n0 = blockIdx.x * BN;

    float acc[8][8];
    #pragma unroll
    for (int i = 0; i < 8; i++)
        #pragma unroll
        for (int j = 0; j < 8; j++) acc[i][j] = 0.f;

    // global tile loads: 2048 floats = 512 float4 per matrix; 2 float4/thread
    int lrow = tid >> 2;            // 0..63
    int lcol = (tid & 3) << 2;      // 0,4,8,12
    const float* Aptr = A + (size_t)(m0 + lrow) * K + lcol;
    const float* Bptr = Bw + (size_t)(n0 + lrow) * K + lcol;

    for (int k0 = 0; k0 < K; k0 += BK) {
        #pragma unroll
        for (int hh = 0; hh < 2; hh++) {
            int r = lrow + hh * 64;
            float4 av = *(const float4*)(Aptr + (size_t)hh * 64 * K + k0);
            float4 bv = *(const float4*)(Bptr + (size_t)hh * 64 * K + k0);
            As[lcol + 0][r] = av.x; As[lcol + 1][r] = av.y;
            As[lcol + 2][r] = av.z; As[lcol + 3][r] = av.w;
            Bs[lcol + 0][r] = bv.x; Bs[lcol + 1][r] = bv.y;
            Bs[lcol + 2][r] = bv.z; Bs[lcol + 3][r] = bv.w;
        }
        __syncthreads();

        #pragma unroll
        for (int k = 0; k < BK; k++) {
            float4 a0 = *(const float4*)&As[k][ty * 4];
            float4 a1 = *(const float4*)&As[k][64 + ty * 4];
            float4 b0 = *(const float4*)&Bs[k][tx * 4];
            float4 b1 = *(const float4*)&Bs[k][64 + tx * 4];
            float ar[8] = {a0.x, a0.y, a0.z, a0.w, a1.x, a1.y, a1.z, a1.w};
            float br[8] = {b0.x, b0.y, b0.z, b0.w, b1.x, b1.y, b1.z, b1.w};
            #pragma unroll
            for (int i = 0; i < 8; i++)
                #pragma unroll
                for (int j = 0; j < 8; j++)
                    acc[i][j] = fmaf(ar[i], br[j], acc[i][j]);
        }
        __syncthreads();
    }

    // epilogue: rows {m0+ty*4+i, m0+64+ty*4+i}, cols {n0+tx*4.., n0+64+tx*4..}
    #pragma unroll
    for (int i = 0; i < 8; i++) {
        int m = m0 + (i < 4 ? ty * 4 + i : 64 + ty * 4 + (i - 4));
        #pragma unroll
        for (int jh = 0; jh < 2; jh++) {
            int n = n0 + jh * 64 + tx * 4;
            float4 bv = *(const float4*)&bias[n];
            float v0 = acc[i][jh * 4 + 0] + bv.x;
            float v1 = acc[i][jh * 4 + 1] + bv.y;
            float v2 = acc[i][jh * 4 + 2] + bv.z;
            float v3 = acc[i][jh * 4 + 3] + bv.w;
            if (EPI == 1) {
                float4 rv = *(const float4*)&R[(size_t)m * N + n];
                v0 += rv.x; v1 += rv.y; v2 += rv.z; v3 += rv.w;
            }
            if (EPI == 2) {
                v0 = 0.5f * v0 * (1.0f + erff(v0 * 0.70710678118f));
                v1 = 0.5f * v1 * (1.0f + erff(v1 * 0.70710678118f));
                v2 = 0.5f * v2 * (1.0f + erff(v2 * 0.70710678118f));
                v3 = 0.5f * v3 * (1.0f + erff(v3 * 0.70710678118f));
            }
            float4 o = {v0, v1, v2, v3};
            *(float4*)&C[(size_t)m * N + n] = o;
        }
    }
}

// ---------------------------------------------------------------------------
// Causal flash attention, fp32. Grid (T/128, B*H). 128 threads; thread = query
// row. Q kept in registers; K/V tiles (64x64) staged in smem (broadcast reads).
// qkv layout: row (b*T+t) has [q(0..E) | k(E..2E) | v(2E..3E)], head h at h*64.
// ---------------------------------------------------------------------------
__global__ __launch_bounds__(128) void attn_kernel(
    const float* __restrict__ qkv, float* __restrict__ att)
{
    __shared__ float Ksm[64 * 64];
    __shared__ float Vsm[64 * 64];

    int b = blockIdx.y >> 4, h = blockIdx.y & 15;
    int q0 = blockIdx.x * 128;
    int tid = threadIdx.x;
    int gq = q0 + tid;

    const float* base = qkv + (size_t)b * 1024 * (3 * EDIM);

    float q[64], o[64];
    {
        const float4* qr = (const float4*)(base + (size_t)gq * (3 * EDIM) + h * 64);
        #pragma unroll
        for (int i = 0; i < 16; i++) {
            float4 v = qr[i];
            q[4*i] = v.x; q[4*i+1] = v.y; q[4*i+2] = v.z; q[4*i+3] = v.w;
        }
    }
    #pragma unroll
    for (int d = 0; d < 64; d++) o[d] = 0.f;
    float m = -1e30f, l = 0.f;

    int ktiles = q0 / 64 + 2;   // covers keys 0 .. q0+127
    for (int kt = 0; kt < ktiles; kt++) {
        __syncthreads();
        #pragma unroll
        for (int i = 0; i < 8; i++) {
            int f = tid + i * 128;            // 0..1023 float4 slots
            int r = f >> 4, c = f & 15;
            const float* krow = base + (size_t)(kt * 64 + r) * (3 * EDIM) + EDIM + h * 64;
            const float* vrow = base + (size_t)(kt * 64 + r) * (3 * EDIM) + 2 * EDIM + h * 64;
            ((float4*)Ksm)[r * 16 + c] = ((const float4*)krow)[c];
            ((float4*)Vsm)[r * 16 + c] = ((const float4*)vrow)[c];
        }
        __syncthreads();

        int smax = min(64, gq - kt * 64 + 1);   // causal: keys s with kt*64+s <= gq
        for (int s = 0; s < smax; s++) {
            const float4* kr = (const float4*)(Ksm + s * 64);
            float dot = 0.f;
            #pragma unroll
            for (int d4 = 0; d4 < 16; d4++) {
                float4 kv = kr[d4];
                dot = fmaf(q[4*d4],   kv.x, dot);
                dot = fmaf(q[4*d4+1], kv.y, dot);
                dot = fmaf(q[4*d4+2], kv.z, dot);
                dot = fmaf(q[4*d4+3], kv.w, dot);
            }
            dot *= 0.125f;   // 1/sqrt(64)
            if (dot > m) {   // rare rescale (online softmax)
                float sc = __expf(m - dot);
                l *= sc;
                #pragma unroll
                for (int d = 0; d < 64; d++) o[d] *= sc;
                m = dot;
            }
            float p = __expf(dot - m);
            l += p;
            const float4* vr = (const float4*)(Vsm + s * 64);
            #pragma unroll
            for (int d4 = 0; d4 < 16; d4++) {
                float4 vv = vr[d4];
                o[4*d4]   = fmaf(p, vv.x, o[4*d4]);
                o[4*d4+1] = fmaf(p, vv.y, o[4*d4+1]);
                o[4*d4+2] = fmaf(p, vv.z, o[4*d4+2]);
                o[4*d4+3] = fmaf(p, vv.w, o[4*d4+3]);
            }
        }
    }

    float inv = 1.0f / l;
    float* orow = att + (size_t)(b * 1024 + gq) * EDIM + h * 64;
    #pragma unroll
    for (int d4 = 0; d4 < 16; d4++) {
        float4 v = { o[4*d4] * inv, o[4*d4+1] * inv, o[4*d4+2] * inv, o[4*d4+3] * inv };
        ((float4*)orow)[d4] = v;
    }
}

// ---------------------------------------------------------------------------
extern "C" void kernel_launch(void* const* d_in, const int* in_sizes, int n_in,
                              void* d_out, int out_size)
{
    const float* x    = (const float*)d_in[0];
    const float* ln1w = (const float*)d_in[1];
    const float* ln1b = (const float*)d_in[2];
    const float* ln2w = (const float*)d_in[3];
    const float* ln2b = (const float*)d_in[4];
    const float* qkvw = (const float*)d_in[5];
    const float* qkvb = (const float*)d_in[6];
    const float* outw = (const float*)d_in[7];
    const float* outb = (const float*)d_in[8];
    const float* fc1w = (const float*)d_in[9];
    const float* fc1b = (const float*)d_in[10];
    const float* fc2w = (const float*)d_in[11];
    const float* fc2b = (const float*)d_in[12];
    float* out = (float*)d_out;

    float *h, *qkv, *att, *x1, *ff;
    cudaGetSymbolAddress((void**)&h,   g_h);
    cudaGetSymbolAddress((void**)&qkv, g_qkv);
    cudaGetSymbolAddress((void**)&att, g_att);
    cudaGetSymbolAddress((void**)&x1,  g_x1);
    cudaGetSymbolAddress((void**)&ff,  g_ff);

    // 1) LN1
    ln_kernel<<<NTOK, 256>>>(x, ln1w, ln1b, h);
    // 2) QKV projection: [4096,1024] @ [3072,1024]^T
    gemm_nt<0><<<dim3(3 * EDIM / 128, NTOK / 128), 256>>>(h, qkvw, qkvb, nullptr, qkv, NTOK, 3 * EDIM, EDIM);
    // 3) causal attention
    attn_kernel<<<dim3(1024 / 128, 4 * NH), 128>>>(qkv, att);
    // 4) output projection + residual(x)
    gemm_nt<1><<<dim3(EDIM / 128, NTOK / 128), 256>>>(att, outw, outb, x, x1, NTOK, EDIM, EDIM);
    // 5) LN2
    ln_kernel<<<NTOK, 256>>>(x1, ln2w, ln2b, h);
    // 6) FC1 + exact GELU
    gemm_nt<2><<<dim3(FDIM / 128, NTOK / 128), 256>>>(h, fc1w, fc1b, nullptr, ff, NTOK, FDIM, EDIM);
    // 7) FC2 + residual(x1) -> out
    gemm_nt<1><<<dim3(EDIM / 128, NTOK / 128), 256>>>(ff, fc2w, fc2b, x1, out, NTOK, EDIM, FDIM);
}

// round 2
// speedup vs baseline: 1.9709x; 1.9709x over previous
#include <cuda_runtime.h>
#include <math.h>
#include <stdint.h>

#define EDIM 1024
#define NTOK 4096          // B*T
#define FDIM 4096
#define NH   16

// ---------------- scratch (__device__ globals; no allocs allowed) ----------
__device__ float g_h  [NTOK * EDIM];            // LN out (tf32-rounded)
__device__ float g_qkv[NTOK * 3 * EDIM];
__device__ float g_att[NTOK * EDIM];            // attn out (tf32-rounded)
__device__ float g_x1 [NTOK * EDIM];
__device__ float g_ff [(size_t)NTOK * FDIM];    // fc1-gelu out (tf32-rounded)
__device__ float g_w  [12 * 1024 * 1024];       // tf32-rounded weights
// offsets (floats) into g_w:
#define OFF_WQKV 0
#define OFF_WOUT (3*1024*1024)
#define OFF_WFC1 (4*1024*1024)
#define OFF_WFC2 (8*1024*1024)

__device__ __forceinline__ float tf32r(float x) {
    unsigned u;
    asm("cvt.rna.tf32.f32 %0, %1;" : "=r"(u) : "f"(x));
    return __uint_as_float(u);
}

// ---------------- weight convert: fp32 -> tf32-rounded fp32 ----------------
__global__ __launch_bounds__(256) void cvt_kernel(
    const float4* __restrict__ src, float4* __restrict__ dst, int n4)
{
    int i = blockIdx.x * 256 + threadIdx.x;
    if (i < n4) {
        float4 v = src[i];
        v.x = tf32r(v.x); v.y = tf32r(v.y); v.z = tf32r(v.z); v.w = tf32r(v.w);
        dst[i] = v;
    }
}

// ---------------- LayerNorm (output tf32-rounded; feeds GEMM A only) -------
__global__ __launch_bounds__(256) void ln_kernel(
    const float* __restrict__ x, const float* __restrict__ w,
    const float* __restrict__ b, float* __restrict__ out)
{
    __shared__ float red[2][8];
    int row = blockIdx.x;
    int tid = threadIdx.x;
    const float4* xr = (const float4*)(x + (size_t)row * EDIM);
    float4 v = xr[tid];
    float s  = v.x + v.y + v.z + v.w;
    float ss = v.x*v.x + v.y*v.y + v.z*v.z + v.w*v.w;
    #pragma unroll
    for (int o = 16; o; o >>= 1) {
        s  += __shfl_xor_sync(0xffffffffu, s,  o);
        ss += __shfl_xor_sync(0xffffffffu, ss, o);
    }
    int wid = tid >> 5, lid = tid & 31;
    if (lid == 0) { red[0][wid] = s; red[1][wid] = ss; }
    __syncthreads();
    s = 0.f; ss = 0.f;
    #pragma unroll
    for (int i = 0; i < 8; i++) { s += red[0][i]; ss += red[1][i]; }
    float mu  = s * (1.0f / EDIM);
    float var = ss * (1.0f / EDIM) - mu * mu;
    float inv = rsqrtf(var + 1e-5f);
    float4 wv = ((const float4*)w)[tid];
    float4 bv = ((const float4*)b)[tid];
    float4 o;
    o.x = tf32r((v.x - mu) * inv * wv.x + bv.x);
    o.y = tf32r((v.y - mu) * inv * wv.y + bv.y);
    o.z = tf32r((v.z - mu) * inv * wv.z + bv.z);
    o.w = tf32r((v.w - mu) * inv * wv.w + bv.w);
    ((float4*)(out + (size_t)row * EDIM))[tid] = o;
}

// ---------------- tf32 tensor-core GEMM  C[M,N] = A[M,K] @ Bw[N,K]^T -------
// 128x128x16 tiles, 256 thr, warps 2(m) x 4(n) -> 64x32 per warp,
// mma.m16n8k8.tf32, double-buffered cp.async.
// smem layout [row][k] stride 20 -> conflict-free frag LDS + STS.128.
// EPI: 0 = +bias, 1 = +bias+residual, 2 = +bias+GELU(exact)+tf32round
__device__ __forceinline__ void mma_tf32(float* d, const unsigned* a, const unsigned* b) {
    asm volatile(
        "mma.sync.aligned.m16n8k8.row.col.f32.tf32.tf32.f32 "
        "{%0,%1,%2,%3},{%4,%5,%6,%7},{%8,%9},{%0,%1,%2,%3};"
        : "+f"(d[0]), "+f"(d[1]), "+f"(d[2]), "+f"(d[3])
        : "r"(a[0]), "r"(a[1]), "r"(a[2]), "r"(a[3]), "r"(b[0]), "r"(b[1]));
}

template <int EPI>
__global__ __launch_bounds__(256) void gemm_tc(
    const float* __restrict__ A, const float* __restrict__ Bw,
    const float* __restrict__ bias, const float* __restrict__ R,
    float* __restrict__ C, int M, int N, int K)
{
    constexpr int LDT = 20;                 // BK(16) + pad(4)
    __shared__ __align__(16) float As[2][128 * LDT];
    __shared__ __align__(16) float Bs[2][128 * LDT];

    int tid  = threadIdx.x;
    int lane = tid & 31, warp = tid >> 5;
    int m0 = blockIdx.y * 128, n0 = blockIdx.x * 128;
    int wm = (warp >> 2) * 64;              // 0 / 64
    int wn = (warp & 3) * 32;               // 0..96

    float acc[4][4][4];
    #pragma unroll
    for (int i = 0; i < 4; i++)
        #pragma unroll
        for (int j = 0; j < 4; j++)
            #pragma unroll
            for (int k = 0; k < 4; k++) acc[i][j][k] = 0.f;

    // loader: 512 float4 per matrix, 2 per thread per matrix
    int lr = tid >> 2;                      // 0..63
    int lk = (tid & 3) << 2;                // 0,4,8,12
    const float* Ag = A  + (size_t)(m0 + lr) * K + lk;
    const float* Bg = Bw + (size_t)(n0 + lr) * K + lk;
    unsigned sA = (unsigned)__cvta_generic_to_shared(&As[0][0]);
    unsigned sB = (unsigned)__cvta_generic_to_shared(&Bs[0][0]);
    unsigned so0 = ((unsigned)(lr * LDT + lk)) * 4u;
    unsigned so1 = ((unsigned)((lr + 64) * LDT + lk)) * 4u;
    constexpr unsigned BUFB = 128u * LDT * 4u;

    int kTiles = K >> 4;

    // prologue: tile 0 -> buf 0
    {
        const float* a0 = Ag;  const float* a1 = Ag + (size_t)64 * K;
        const float* b0 = Bg;  const float* b1 = Bg + (size_t)64 * K;
        asm volatile("cp.async.cg.shared.global [%0], [%1], 16;\n" :: "r"(sA + so0), "l"(a0));
        asm volatile("cp.async.cg.shared.global [%0], [%1], 16;\n" :: "r"(sA + so1), "l"(a1));
        asm volatile("cp.async.cg.shared.global [%0], [%1], 16;\n" :: "r"(sB + so0), "l"(b0));
        asm volatile("cp.async.cg.shared.global [%0], [%1], 16;\n" :: "r"(sB + so1), "l"(b1));
        asm volatile("cp.async.commit_group;\n");
    }

    int q = lane >> 2, c = lane & 3;
    // per-thread frag base offsets (in floats) within a buffer
    unsigned abase[4], bbase[4];
    #pragma unroll
    for (int mt = 0; mt < 4; mt++) abase[mt] = (wm + mt * 16 + q) * LDT + c;
    #pragma unroll
    for (int nt = 0; nt < 4; nt++) bbase[nt] = (wn + nt * 8 + q) * LDT + c;

    for (int t = 0; t < kTiles; t++) {
        asm volatile("cp.async.wait_group 0;\n");
        __syncthreads();

        if (t + 1 < kTiles) {
            int kb = (t + 1) << 4;
            unsigned boff = ((t + 1) & 1) ? BUFB : 0u;
            const float* a0 = Ag + kb;  const float* a1 = Ag + (size_t)64 * K + kb;
            const float* b0 = Bg + kb;  const float* b1 = Bg + (size_t)64 * K + kb;
            asm volatile("cp.async.cg.shared.global [%0], [%1], 16;\n" :: "r"(sA + boff + so0), "l"(a0));
            asm volatile("cp.async.cg.shared.global [%0], [%1], 16;\n" :: "r"(sA + boff + so1), "l"(a1));
            asm volatile("cp.async.cg.shared.global [%0], [%1], 16;\n" :: "r"(sB + boff + so0), "l"(b0));
            asm volatile("cp.async.cg.shared.global [%0], [%1], 16;\n" :: "r"(sB + boff + so1), "l"(b1));
            asm volatile("cp.async.commit_group;\n");
        }

        const unsigned* Au = (const unsigned*)As[t & 1];
        const unsigned* Bu = (const unsigned*)Bs[t & 1];

        #pragma unroll
        for (int ks = 0; ks < 2; ks++) {
            int ko = ks * 8;
            unsigned a[4][4], b[4][2];
            #pragma unroll
            for (int mt = 0; mt < 4; mt++) {
                unsigned base = abase[mt] + ko;
                a[mt][0] = Au[base];
                a[mt][1] = Au[base + 8 * LDT];
                a[mt][2] = Au[base + 4];
                a[mt][3] = Au[base + 8 * LDT + 4];
            }
            #pragma unroll
            for (int nt = 0; nt < 4; nt++) {
                unsigned base = bbase[nt] + ko;
                b[nt][0] = Bu[base];
                b[nt][1] = Bu[base + 4];
            }
            #pragma unroll
            for (int mt = 0; mt < 4; mt++)
                #pragma unroll
                for (int nt = 0; nt < 4; nt++)
                    mma_tf32(acc[mt][nt], a[mt], b[nt]);
        }
        __syncthreads();
    }

    // epilogue
    int cc = (lane & 3) * 2;
    #pragma unroll
    for (int mt = 0; mt < 4; mt++) {
        #pragma unroll
        for (int nt = 0; nt < 4; nt++) {
            int row = m0 + wm + mt * 16 + q;
            int col = n0 + wn + nt * 8 + cc;
            float bx = bias[col], by = bias[col + 1];
            float v0 = acc[mt][nt][0] + bx, v1 = acc[mt][nt][1] + by;
            float v2 = acc[mt][nt][2] + bx, v3 = acc[mt][nt][3] + by;
            if (EPI == 1) {
                float2 r0 = *(const float2*)&R[(size_t)row * N + col];
                float2 r1 = *(const float2*)&R[(size_t)(row + 8) * N + col];
                v0 += r0.x; v1 += r0.y; v2 += r1.x; v3 += r1.y;
            }
            if (EPI == 2) {
                v0 = tf32r(0.5f * v0 * (1.0f + erff(v0 * 0.70710678118f)));
                v1 = tf32r(0.5f * v1 * (1.0f + erff(v1 * 0.70710678118f)));
                v2 = tf32r(0.5f * v2 * (1.0f + erff(v2 * 0.70710678118f)));
                v3 = tf32r(0.5f * v3 * (1.0f + erff(v3 * 0.70710678118f)));
            }
            float2 o0 = {v0, v1}, o1 = {v2, v3};
            *(float2*)&C[(size_t)row * N + col] = o0;
            *(float2*)&C[(size_t)(row + 8) * N + col] = o1;
        }
    }
}

// ---------------- causal flash attention (fp32), output tf32-rounded -------
__global__ __launch_bounds__(128) void attn_kernel(
    const float* __restrict__ qkv, float* __restrict__ att)
{
    __shared__ float Ksm[64 * 64];
    __shared__ float Vsm[64 * 64];

    int b = blockIdx.y >> 4, h = blockIdx.y & 15;
    int q0 = blockIdx.x * 128;
    int tid = threadIdx.x;
    int gq = q0 + tid;

    const float* base = qkv + (size_t)b * 1024 * (3 * EDIM);

    float q[64], o[64];
    {
        const float4* qr = (const float4*)(base + (size_t)gq * (3 * EDIM) + h * 64);
        #pragma unroll
        for (int i = 0; i < 16; i++) {
            float4 v = qr[i];
            q[4*i] = v.x; q[4*i+1] = v.y; q[4*i+2] = v.z; q[4*i+3] = v.w;
        }
    }
    #pragma unroll
    for (int d = 0; d < 64; d++) o[d] = 0.f;
    float m = -1e30f, l = 0.f;

    int ktiles = q0 / 64 + 2;
    for (int kt = 0; kt < ktiles; kt++) {
        __syncthreads();
        #pragma unroll
        for (int i = 0; i < 8; i++) {
            int f = tid + i * 128;
            int r = f >> 4, cidx = f & 15;
            const float* krow = base + (size_t)(kt * 64 + r) * (3 * EDIM) + EDIM + h * 64;
            const float* vrow = base + (size_t)(kt * 64 + r) * (3 * EDIM) + 2 * EDIM + h * 64;
            ((float4*)Ksm)[r * 16 + cidx] = ((const float4*)krow)[cidx];
            ((float4*)Vsm)[r * 16 + cidx] = ((const float4*)vrow)[cidx];
        }
        __syncthreads();

        int smax = min(64, gq - kt * 64 + 1);
        for (int s = 0; s < smax; s++) {
            const float4* kr = (const float4*)(Ksm + s * 64);
            float dot = 0.f;
            #pragma unroll
            for (int d4 = 0; d4 < 16; d4++) {
                float4 kv = kr[d4];
                dot = fmaf(q[4*d4],   kv.x, dot);
                dot = fmaf(q[4*d4+1], kv.y, dot);
                dot = fmaf(q[4*d4+2], kv.z, dot);
                dot = fmaf(q[4*d4+3], kv.w, dot);
            }
            dot *= 0.125f;
            if (dot > m) {
                float sc = __expf(m - dot);
                l *= sc;
                #pragma unroll
                for (int d = 0; d < 64; d++) o[d] *= sc;
                m = dot;
            }
            float p = __expf(dot - m);
            l += p;
            const float4* vr = (const float4*)(Vsm + s * 64);
            #pragma unroll
            for (int d4 = 0; d4 < 16; d4++) {
                float4 vv = vr[d4];
                o[4*d4]   = fmaf(p, vv.x, o[4*d4]);
                o[4*d4+1] = fmaf(p, vv.y, o[4*d4+1]);
                o[4*d4+2] = fmaf(p, vv.z, o[4*d4+2]);
                o[4*d4+3] = fmaf(p, vv.w, o[4*d4+3]);
            }
        }
    }

    float inv = 1.0f / l;
    float* orow = att + (size_t)(b * 1024 + gq) * EDIM + h * 64;
    #pragma unroll
    for (int d4 = 0; d4 < 16; d4++) {
        float4 v = { tf32r(o[4*d4] * inv), tf32r(o[4*d4+1] * inv),
                     tf32r(o[4*d4+2] * inv), tf32r(o[4*d4+3] * inv) };
        ((float4*)orow)[d4] = v;
    }
}

// ---------------------------------------------------------------------------
extern "C" void kernel_launch(void* const* d_in, const int* in_sizes, int n_in,
                              void* d_out, int out_size)
{
    const float* x    = (const float*)d_in[0];
    const float* ln1w = (const float*)d_in[1];
    const float* ln1b = (const float*)d_in[2];
    const float* ln2w = (const float*)d_in[3];
    const float* ln2b = (const float*)d_in[4];
    const float* qkvw = (const float*)d_in[5];
    const float* qkvb = (const float*)d_in[6];
    const float* outw = (const float*)d_in[7];
    const float* outb = (const float*)d_in[8];
    const float* fc1w = (const float*)d_in[9];
    const float* fc1b = (const float*)d_in[10];
    const float* fc2w = (const float*)d_in[11];
    const float* fc2b = (const float*)d_in[12];
    float* out = (float*)d_out;

    float *h, *qkv, *att, *x1, *ff, *w;
    cudaGetSymbolAddress((void**)&h,   g_h);
    cudaGetSymbolAddress((void**)&qkv, g_qkv);
    cudaGetSymbolAddress((void**)&att, g_att);
    cudaGetSymbolAddress((void**)&x1,  g_x1);
    cudaGetSymbolAddress((void**)&ff,  g_ff);
    cudaGetSymbolAddress((void**)&w,   g_w);

    float* wq = w + OFF_WQKV;
    float* wo = w + OFF_WOUT;
    float* w1 = w + OFF_WFC1;
    float* w2 = w + OFF_WFC2;

    // 0) weights -> tf32-rounded copies
    cvt_kernel<<<(3*1024*1024/4 + 255)/256, 256>>>((const float4*)qkvw, (float4*)wq, 3*1024*1024/4);
    cvt_kernel<<<(1024*1024/4   + 255)/256, 256>>>((const float4*)outw, (float4*)wo, 1024*1024/4);
    cvt_kernel<<<(4*1024*1024/4 + 255)/256, 256>>>((const float4*)fc1w, (float4*)w1, 4*1024*1024/4);
    cvt_kernel<<<(4*1024*1024/4 + 255)/256, 256>>>((const float4*)fc2w, (float4*)w2, 4*1024*1024/4);

    // 1) LN1 (tf32-rounded out)
    ln_kernel<<<NTOK, 256>>>(x, ln1w, ln1b, h);
    // 2) QKV projection
    gemm_tc<0><<<dim3(3*EDIM/128, NTOK/128), 256>>>(h, wq, qkvb, nullptr, qkv, NTOK, 3*EDIM, EDIM);
    // 3) attention (tf32-rounded out)
    attn_kernel<<<dim3(1024/128, 4*NH), 128>>>(qkv, att);
    // 4) out projection + residual(x)
    gemm_tc<1><<<dim3(EDIM/128, NTOK/128), 256>>>(att, wo, outb, x, x1, NTOK, EDIM, EDIM);
    // 5) LN2
    ln_kernel<<<NTOK, 256>>>(x1, ln2w, ln2b, h);
    // 6) FC1 + GELU (tf32-rounded out)
    gemm_tc<2><<<dim3(FDIM/128, NTOK/128), 256>>>(h, w1, fc1b, nullptr, ff, NTOK, FDIM, EDIM);
    // 7) FC2 + residual(x1) -> out
    gemm_tc<1><<<dim3(EDIM/128, NTOK/128), 256>>>(ff, w2, fc2b, x1, out, NTOK, EDIM, FDIM);
}

// round 4
// speedup vs baseline: 2.0138x; 1.0218x over previous
#include <cuda_runtime.h>
#include <math.h>
#include <stdint.h>

#define EDIM 1024
#define NTOK 4096          // B*T
#define FDIM 4096
#define NH   16

// ---------------- scratch (__device__ globals; no allocs allowed) ----------
__device__ float g_h  [NTOK * EDIM];            // LN out (tf32-rounded)
__device__ float g_qkv[NTOK * 3 * EDIM];
__device__ float g_att[NTOK * EDIM];            // attn out (tf32-rounded)
__device__ float g_x1 [NTOK * EDIM];
__device__ float g_ff [(size_t)NTOK * FDIM];    // fc1-gelu out (tf32-rounded)
__device__ float g_w  [12 * 1024 * 1024];       // tf32-rounded weights
#define OFF_WQKV 0
#define OFF_WOUT (3*1024*1024)
#define OFF_WFC1 (4*1024*1024)
#define OFF_WFC2 (8*1024*1024)

__device__ __forceinline__ float tf32r(float x) {
    unsigned u;
    asm("cvt.rna.tf32.f32 %0, %1;" : "=r"(u) : "f"(x));
    return __uint_as_float(u);
}

__device__ __forceinline__ uint32_t smem_u32(const void* p) {
    uint32_t a;
    asm("{ .reg .u64 t; cvta.to.shared.u64 t, %1; cvt.u32.u64 %0, t; }" : "=r"(a) : "l"(p));
    return a;
}

__device__ __forceinline__ void mma_tf32(float* d, const unsigned* a, const unsigned* b) {
    asm volatile(
        "mma.sync.aligned.m16n8k8.row.col.f32.tf32.tf32.f32 "
        "{%0,%1,%2,%3},{%4,%5,%6,%7},{%8,%9},{%0,%1,%2,%3};"
        : "+f"(d[0]), "+f"(d[1]), "+f"(d[2]), "+f"(d[3])
        : "r"(a[0]), "r"(a[1]), "r"(a[2]), "r"(a[3]), "r"(b[0]), "r"(b[1]));
}

// ---------------- weight convert: fp32 -> tf32-rounded fp32 ----------------
__global__ __launch_bounds__(256) void cvt_kernel(
    const float4* __restrict__ src, float4* __restrict__ dst, int n4)
{
    int i = blockIdx.x * 256 + threadIdx.x;
    if (i < n4) {
        float4 v = src[i];
        v.x = tf32r(v.x); v.y = tf32r(v.y); v.z = tf32r(v.z); v.w = tf32r(v.w);
        dst[i] = v;
    }
}

// ---------------- LayerNorm (output tf32-rounded) --------------------------
__global__ __launch_bounds__(256) void ln_kernel(
    const float* __restrict__ x, const float* __restrict__ w,
    const float* __restrict__ b, float* __restrict__ out)
{
    __shared__ float red[2][8];
    int row = blockIdx.x;
    int tid = threadIdx.x;
    const float4* xr = (const float4*)(x + (size_t)row * EDIM);
    float4 v = xr[tid];
    float s  = v.x + v.y + v.z + v.w;
    float ss = v.x*v.x + v.y*v.y + v.z*v.z + v.w*v.w;
    #pragma unroll
    for (int o = 16; o; o >>= 1) {
        s  += __shfl_xor_sync(0xffffffffu, s,  o);
        ss += __shfl_xor_sync(0xffffffffu, ss, o);
    }
    int wid = tid >> 5, lid = tid & 31;
    if (lid == 0) { red[0][wid] = s; red[1][wid] = ss; }
    __syncthreads();
    s = 0.f; ss = 0.f;
    #pragma unroll
    for (int i = 0; i < 8; i++) { s += red[0][i]; ss += red[1][i]; }
    float mu  = s * (1.0f / EDIM);
    float var = ss * (1.0f / EDIM) - mu * mu;
    float inv = rsqrtf(var + 1e-5f);
    float4 wv = ((const float4*)w)[tid];
    float4 bv = ((const float4*)b)[tid];
    float4 o;
    o.x = tf32r((v.x - mu) * inv * wv.x + bv.x);
    o.y = tf32r((v.y - mu) * inv * wv.y + bv.y);
    o.z = tf32r((v.z - mu) * inv * wv.z + bv.z);
    o.w = tf32r((v.w - mu) * inv * wv.w + bv.w);
    ((float4*)(out + (size_t)row * EDIM))[tid] = o;
}

// ---------------------------------------------------------------------------
// tf32 mma.sync GEMM.  C[M,N] = A[M,K] @ Bw[N,K]^T  (both row-major NT)
// Tile 128x256xBK16; 8 warps as 2(m) x 4(n) -> 64x64 warp tiles.
// 3-stage cp.async pipeline. smem rows padded to LDT=20 (conflict-free frags).
// EPI: 0 = +bias, 1 = +bias+residual, 2 = +bias+GELU+tf32round
// ---------------------------------------------------------------------------
template <int EPI>
__global__ __launch_bounds__(256, 1) void gemm_tc(
    const float* __restrict__ A, const float* __restrict__ Bw,
    const float* __restrict__ bias, const float* __restrict__ R,
    float* __restrict__ C, int M, int N, int K)
{
    constexpr int BM = 128, BN = 256, LDT = 20, NST = 3;
    constexpr uint32_t AOFF  = BM * LDT * 4;            // bytes: B region offset
    constexpr uint32_t STAGE = (BM + BN) * LDT * 4;     // bytes per stage

    extern __shared__ char dsm[];
    uint32_t sb = smem_u32(dsm);
    int tid = threadIdx.x, warp = tid >> 5, lane = tid & 31;
    int m0 = blockIdx.y * BM, n0 = blockIdx.x * BN;
    int wm = (warp >> 2) * 64;        // 0 / 64
    int wn = (warp & 3) * 64;         // 0..192
    int T = K >> 4;

    float acc[4][8][4];
    #pragma unroll
    for (int i = 0; i < 4; i++)
        #pragma unroll
        for (int j = 0; j < 8; j++)
            #pragma unroll
            for (int k = 0; k < 4; k++) acc[i][j][k] = 0.f;

    auto load_tile = [&](int t, int s) {
        int k0 = t << 4;
        uint32_t base = sb + (uint32_t)s * STAGE;
        #pragma unroll
        for (int j = 0; j < 6; j++) {
            int idx = tid + j * 256;            // 0..1535 float4 slots
            bool isB = idx >= 512;
            int r  = isB ? ((idx - 512) >> 2) : (idx >> 2);
            int kc = (idx & 3) << 2;
            const float* g = isB ? (Bw + (size_t)(n0 + r) * K + k0 + kc)
                                 : (A  + (size_t)(m0 + r) * K + k0 + kc);
            uint32_t dst = base + (isB ? AOFF : 0u) + (uint32_t)(r * LDT + kc) * 4u;
            asm volatile("cp.async.cg.shared.global [%0], [%1], 16;" :: "r"(dst), "l"(g));
        }
    };

    // prologue: stages 0,1
    load_tile(0, 0);
    asm volatile("cp.async.commit_group;" ::: "memory");
    load_tile(1, 1);
    asm volatile("cp.async.commit_group;" ::: "memory");

    int q = lane >> 2, c = lane & 3;
    unsigned abase[4], bbase[8];
    #pragma unroll
    for (int mt = 0; mt < 4; mt++) abase[mt] = (wm + mt * 16 + q) * LDT + c;
    #pragma unroll
    for (int nt = 0; nt < 8; nt++) bbase[nt] = (wn + nt * 8 + q) * LDT + c;

    for (int t = 0; t < T; t++) {
        asm volatile("cp.async.wait_group 1;" ::: "memory");
        __syncthreads();

        if (t + 2 < T) load_tile(t + 2, (t + 2) % NST);
        asm volatile("cp.async.commit_group;" ::: "memory");

        const unsigned* Au = (const unsigned*)(dsm + (size_t)(t % NST) * STAGE);
        const unsigned* Bu = Au + BM * LDT;

        #pragma unroll
        for (int ks = 0; ks < 2; ks++) {
            int ko = ks * 8;
            unsigned a[4][4], b[8][2];
            #pragma unroll
            for (int mt = 0; mt < 4; mt++) {
                unsigned base = abase[mt] + ko;
                a[mt][0] = Au[base];
                a[mt][1] = Au[base + 8 * LDT];
                a[mt][2] = Au[base + 4];
                a[mt][3] = Au[base + 8 * LDT + 4];
            }
            #pragma unroll
            for (int nt = 0; nt < 8; nt++) {
                unsigned base = bbase[nt] + ko;
                b[nt][0] = Bu[base];
                b[nt][1] = Bu[base + 4];
            }
            #pragma unroll
            for (int mt = 0; mt < 4; mt++)
                #pragma unroll
                for (int nt = 0; nt < 8; nt++)
                    mma_tf32(acc[mt][nt], a[mt], b[nt]);
        }
    }

    // epilogue
    int cc = (lane & 3) * 2;
    #pragma unroll
    for (int mt = 0; mt < 4; mt++) {
        #pragma unroll
        for (int nt = 0; nt < 8; nt++) {
            int row = m0 + wm + mt * 16 + q;
            int col = n0 + wn + nt * 8 + cc;
            float bx = bias[col], by = bias[col + 1];
            float v0 = acc[mt][nt][0] + bx, v1 = acc[mt][nt][1] + by;
            float v2 = acc[mt][nt][2] + bx, v3 = acc[mt][nt][3] + by;
            if (EPI == 1) {
                float2 r0 = *(const float2*)&R[(size_t)row * N + col];
                float2 r1 = *(const float2*)&R[(size_t)(row + 8) * N + col];
                v0 += r0.x; v1 += r0.y; v2 += r1.x; v3 += r1.y;
            }
            if (EPI == 2) {
                v0 = tf32r(0.5f * v0 * (1.0f + erff(v0 * 0.70710678118f)));
                v1 = tf32r(0.5f * v1 * (1.0f + erff(v1 * 0.70710678118f)));
                v2 = tf32r(0.5f * v2 * (1.0f + erff(v2 * 0.70710678118f)));
                v3 = tf32r(0.5f * v3 * (1.0f + erff(v3 * 0.70710678118f)));
            }
            float2 o0 = {v0, v1}, o1 = {v2, v3};
            *(float2*)&C[(size_t)row * N + col] = o0;
            *(float2*)&C[(size_t)(row + 8) * N + col] = o1;
        }
    }
}

// ---------------- causal flash attention (fp32), output tf32-rounded -------
__global__ __launch_bounds__(128) void attn_kernel(
    const float* __restrict__ qkv, float* __restrict__ att)
{
    __shared__ float Ksm[64 * 64];
    __shared__ float Vsm[64 * 64];

    int b = blockIdx.y >> 4, h = blockIdx.y & 15;
    int q0 = blockIdx.x * 128;
    int tid = threadIdx.x;
    int gq = q0 + tid;

    const float* base = qkv + (size_t)b * 1024 * (3 * EDIM);

    float q[64], o[64];
    {
        const float4* qr = (const float4*)(base + (size_t)gq * (3 * EDIM) + h * 64);
        #pragma unroll
        for (int i = 0; i < 16; i++) {
            float4 v = qr[i];
            q[4*i] = v.x; q[4*i+1] = v.y; q[4*i+2] = v.z; q[4*i+3] = v.w;
        }
    }
    #pragma unroll
    for (int d = 0; d < 64; d++) o[d] = 0.f;
    float m = -1e30f, l = 0.f;

    int ktiles = q0 / 64 + 2;
    for (int kt = 0; kt < ktiles; kt++) {
        __syncthreads();
        #pragma unroll
        for (int i = 0; i < 8; i++) {
            int f = tid + i * 128;
            int r = f >> 4, cidx = f & 15;
            const float* krow = base + (size_t)(kt * 64 + r) * (3 * EDIM) + EDIM + h * 64;
            const float* vrow = base + (size_t)(kt * 64 + r) * (3 * EDIM) + 2 * EDIM + h * 64;
            ((float4*)Ksm)[r * 16 + cidx] = ((const float4*)krow)[cidx];
            ((float4*)Vsm)[r * 16 + cidx] = ((const float4*)vrow)[cidx];
        }
        __syncthreads();

        int smax = min(64, gq - kt * 64 + 1);
        for (int s = 0; s < smax; s++) {
            const float4* kr = (const float4*)(Ksm + s * 64);
            float dot = 0.f;
            #pragma unroll
            for (int d4 = 0; d4 < 16; d4++) {
                float4 kv = kr[d4];
                dot = fmaf(q[4*d4],   kv.x, dot);
                dot = fmaf(q[4*d4+1], kv.y, dot);
                dot = fmaf(q[4*d4+2], kv.z, dot);
                dot = fmaf(q[4*d4+3], kv.w, dot);
            }
            dot *= 0.125f;
            if (dot > m) {
                float sc = __expf(m - dot);
                l *= sc;
                #pragma unroll
                for (int d = 0; d < 64; d++) o[d] *= sc;
                m = dot;
            }
            float p = __expf(dot - m);
            l += p;
            const float4* vr = (const float4*)(Vsm + s * 64);
            #pragma unroll
            for (int d4 = 0; d4 < 16; d4++) {
                float4 vv = vr[d4];
                o[4*d4]   = fmaf(p, vv.x, o[4*d4]);
                o[4*d4+1] = fmaf(p, vv.y, o[4*d4+1]);
                o[4*d4+2] = fmaf(p, vv.z, o[4*d4+2]);
                o[4*d4+3] = fmaf(p, vv.w, o[4*d4+3]);
            }
        }
    }

    float inv = 1.0f / l;
    float* orow = att + (size_t)(b * 1024 + gq) * EDIM + h * 64;
    #pragma unroll
    for (int d4 = 0; d4 < 16; d4++) {
        float4 v = { tf32r(o[4*d4] * inv), tf32r(o[4*d4+1] * inv),
                     tf32r(o[4*d4+2] * inv), tf32r(o[4*d4+3] * inv) };
        ((float4*)orow)[d4] = v;
    }
}

// ---------------------------------------------------------------------------
extern "C" void kernel_launch(void* const* d_in, const int* in_sizes, int n_in,
                              void* d_out, int out_size)
{
    const float* x    = (const float*)d_in[0];
    const float* ln1w = (const float*)d_in[1];
    const float* ln1b = (const float*)d_in[2];
    const float* ln2w = (const float*)d_in[3];
    const float* ln2b = (const float*)d_in[4];
    const float* qkvw = (const float*)d_in[5];
    const float* qkvb = (const float*)d_in[6];
    const float* outw = (const float*)d_in[7];
    const float* outb = (const float*)d_in[8];
    const float* fc1w = (const float*)d_in[9];
    const float* fc1b = (const float*)d_in[10];
    const float* fc2w = (const float*)d_in[11];
    const float* fc2b = (const float*)d_in[12];
    float* out = (float*)d_out;

    float *h, *qkv, *att, *x1, *ff, *w;
    cudaGetSymbolAddress((void**)&h,   g_h);
    cudaGetSymbolAddress((void**)&qkv, g_qkv);
    cudaGetSymbolAddress((void**)&att, g_att);
    cudaGetSymbolAddress((void**)&x1,  g_x1);
    cudaGetSymbolAddress((void**)&ff,  g_ff);
    cudaGetSymbolAddress((void**)&w,   g_w);

    float* wq = w + OFF_WQKV;
    float* wo = w + OFF_WOUT;
    float* w1 = w + OFF_WFC1;
    float* w2 = w + OFF_WFC2;

    const int SMEM = 3 * (128 + 256) * 20 * 4;   // 92160 bytes
    cudaFuncSetAttribute(gemm_tc<0>, cudaFuncAttributeMaxDynamicSharedMemorySize, SMEM);
    cudaFuncSetAttribute(gemm_tc<1>, cudaFuncAttributeMaxDynamicSharedMemorySize, SMEM);
    cudaFuncSetAttribute(gemm_tc<2>, cudaFuncAttributeMaxDynamicSharedMemorySize, SMEM);

    // 0) weights -> tf32-rounded copies
    cvt_kernel<<<(3*1024*1024/4 + 255)/256, 256>>>((const float4*)qkvw, (float4*)wq, 3*1024*1024/4);
    cvt_kernel<<<(1024*1024/4   + 255)/256, 256>>>((const float4*)outw, (float4*)wo, 1024*1024/4);
    cvt_kernel<<<(4*1024*1024/4 + 255)/256, 256>>>((const float4*)fc1w, (float4*)w1, 4*1024*1024/4);
    cvt_kernel<<<(4*1024*1024/4 + 255)/256, 256>>>((const float4*)fc2w, (float4*)w2, 4*1024*1024/4);

    // 1) LN1
    ln_kernel<<<NTOK, 256>>>(x, ln1w, ln1b, h);
    // 2) QKV projection: [4096,3072,1024]
    gemm_tc<0><<<dim3(3*EDIM/256, NTOK/128), 256, SMEM>>>(h, wq, qkvb, nullptr, qkv, NTOK, 3*EDIM, EDIM);
    // 3) attention
    attn_kernel<<<dim3(1024/128, 4*NH), 128>>>(qkv, att);
    // 4) out projection + residual(x)
    gemm_tc<1><<<dim3(EDIM/256, NTOK/128), 256, SMEM>>>(att, wo, outb, x, x1, NTOK, EDIM, EDIM);
    // 5) LN2
    ln_kernel<<<NTOK, 256>>>(x1, ln2w, ln2b, h);
    // 6) FC1 + GELU
    gemm_tc<2><<<dim3(FDIM/256, NTOK/128), 256, SMEM>>>(h, w1, fc1b, nullptr, ff, NTOK, FDIM, EDIM);
    // 7) FC2 + residual(x1) -> out
    gemm_tc<1><<<dim3(EDIM/256, NTOK/128), 256, SMEM>>>(ff, w2, fc2b, x1, out, NTOK, EDIM, FDIM);
}

// round 5
// speedup vs baseline: 2.8309x; 1.4058x over previous
#include <cuda_runtime.h>
#include <cuda_bf16.h>
#include <math.h>
#include <stdint.h>

#define EDIM 1024
#define NTOK 4096          // B*T
#define FDIM 4096
#define NH   16

// ---------------- scratch (__device__ globals; no allocs allowed) ----------
__device__ __nv_bfloat16 g_h  [NTOK * EDIM];            // LN out (bf16)
__device__ float         g_qkv[NTOK * 3 * EDIM];        // fp32 (attn input)
__device__ __nv_bfloat16 g_att[NTOK * EDIM];            // attn out (bf16)
__device__ float         g_x1 [NTOK * EDIM];            // residual after attn
__device__ __nv_bfloat16 g_ff [(size_t)NTOK * FDIM];    // fc1-gelu out (bf16)
__device__ __nv_bfloat16 g_w  [12 * 1024 * 1024];       // bf16 weights
#define OFF_WQKV 0
#define OFF_WOUT (3*1024*1024)
#define OFF_WFC1 (4*1024*1024)
#define OFF_WFC2 (8*1024*1024)

__device__ __forceinline__ unsigned bfpack(float lo, float hi) {
    __nv_bfloat162 p = __floats2bfloat162_rn(lo, hi);
    return *(unsigned*)&p;
}

__device__ __forceinline__ void mma_bf16(float* d, const unsigned* a, const unsigned* b) {
    asm volatile(
        "mma.sync.aligned.m16n8k16.row.col.f32.bf16.bf16.f32 "
        "{%0,%1,%2,%3},{%4,%5,%6,%7},{%8,%9},{%0,%1,%2,%3};"
        : "+f"(d[0]), "+f"(d[1]), "+f"(d[2]), "+f"(d[3])
        : "r"(a[0]), "r"(a[1]), "r"(a[2]), "r"(a[3]), "r"(b[0]), "r"(b[1]));
}

// ---------------- weight convert: fp32 -> bf16 -----------------------------
__global__ __launch_bounds__(256) void cvt_kernel(
    const float4* __restrict__ src, __nv_bfloat16* __restrict__ dst, int n4)
{
    int i = blockIdx.x * 256 + threadIdx.x;
    if (i < n4) {
        float4 v = src[i];
        uint2 o = { bfpack(v.x, v.y), bfpack(v.z, v.w) };
        ((uint2*)dst)[i] = o;
    }
}

// ---------------- LayerNorm (fp32 in, bf16 out) ----------------------------
__global__ __launch_bounds__(256) void ln_kernel(
    const float* __restrict__ x, const float* __restrict__ w,
    const float* __restrict__ b, __nv_bfloat16* __restrict__ out)
{
    __shared__ float red[2][8];
    int row = blockIdx.x;
    int tid = threadIdx.x;
    const float4* xr = (const float4*)(x + (size_t)row * EDIM);
    float4 v = xr[tid];
    float s  = v.x + v.y + v.z + v.w;
    float ss = v.x*v.x + v.y*v.y + v.z*v.z + v.w*v.w;
    #pragma unroll
    for (int o = 16; o; o >>= 1) {
        s  += __shfl_xor_sync(0xffffffffu, s,  o);
        ss += __shfl_xor_sync(0xffffffffu, ss, o);
    }
    int wid = tid >> 5, lid = tid & 31;
    if (lid == 0) { red[0][wid] = s; red[1][wid] = ss; }
    __syncthreads();
    s = 0.f; ss = 0.f;
    #pragma unroll
    for (int i = 0; i < 8; i++) { s += red[0][i]; ss += red[1][i]; }
    float mu  = s * (1.0f / EDIM);
    float var = ss * (1.0f / EDIM) - mu * mu;
    float inv = rsqrtf(var + 1e-5f);
    float4 wv = ((const float4*)w)[tid];
    float4 bv = ((const float4*)b)[tid];
    float o0 = (v.x - mu) * inv * wv.x + bv.x;
    float o1 = (v.y - mu) * inv * wv.y + bv.y;
    float o2 = (v.z - mu) * inv * wv.z + bv.z;
    float o3 = (v.w - mu) * inv * wv.w + bv.w;
    uint2 o = { bfpack(o0, o1), bfpack(o2, o3) };
    ((uint2*)(out + (size_t)row * EDIM))[tid] = o;
}

// ---------------------------------------------------------------------------
// bf16 mma.sync GEMM.  C[M,N] = A[M,K] @ Bw[N,K]^T  (both row-major NT, bf16)
// Tile 128x256xBK32; 8 warps as 2(m) x 4(n) -> 64x64 warp tiles.
// smem word = bf16x2 along k; 16 words/row padded to LDT=20.
// 3-stage cp.async pipeline; fp32 accum.
// EPI: 0 = +bias -> fp32 C;  1 = +bias+residual -> fp32 C;
//      2 = +bias+GELU(exact) -> bf16 C
// ---------------------------------------------------------------------------
template <int EPI>
__global__ __launch_bounds__(256, 1) void gemm_tc(
    const __nv_bfloat16* __restrict__ A, const __nv_bfloat16* __restrict__ Bw,
    const float* __restrict__ bias, const float* __restrict__ R,
    void* __restrict__ Cv, int M, int N, int K)
{
    constexpr int BM = 128, BN = 256, LDT = 20, NST = 3;  // LDT in 4-byte words
    constexpr uint32_t AOFF  = BM * LDT * 4;
    constexpr uint32_t STAGE = (BM + BN) * LDT * 4;

    extern __shared__ char dsm[];
    uint32_t sb;
    asm("{ .reg .u64 t; cvta.to.shared.u64 t, %1; cvt.u32.u64 %0, t; }" : "=r"(sb) : "l"(dsm));
    int tid = threadIdx.x, warp = tid >> 5, lane = tid & 31;
    int m0 = blockIdx.y * BM, n0 = blockIdx.x * BN;
    int wm = (warp >> 2) * 64;
    int wn = (warp & 3) * 64;
    int T = K >> 5;

    float acc[4][8][4];
    #pragma unroll
    for (int i = 0; i < 4; i++)
        #pragma unroll
        for (int j = 0; j < 8; j++)
            #pragma unroll
            for (int k = 0; k < 4; k++) acc[i][j][k] = 0.f;

    auto load_tile = [&](int t, int s) {
        int k0 = t << 5;
        uint32_t base = sb + (uint32_t)s * STAGE;
        #pragma unroll
        for (int j = 0; j < 6; j++) {
            int idx = tid + j * 256;            // 1536 16B-chunks per stage
            bool isB = idx >= 512;
            int r  = isB ? ((idx - 512) >> 2) : (idx >> 2);
            int ch = idx & 3;                   // 8 bf16 per chunk
            const __nv_bfloat16* g = isB ? (Bw + (size_t)(n0 + r) * K + k0 + ch * 8)
                                         : (A  + (size_t)(m0 + r) * K + k0 + ch * 8);
            uint32_t dst = base + (isB ? AOFF : 0u) + (uint32_t)(r * LDT + ch * 4) * 4u;
            asm volatile("cp.async.cg.shared.global [%0], [%1], 16;" :: "r"(dst), "l"(g));
        }
    };

    load_tile(0, 0);
    asm volatile("cp.async.commit_group;" ::: "memory");
    load_tile(1, 1);
    asm volatile("cp.async.commit_group;" ::: "memory");

    int q = lane >> 2, c = lane & 3;
    unsigned abase[4], bbase[8];
    #pragma unroll
    for (int mt = 0; mt < 4; mt++) abase[mt] = (wm + mt * 16 + q) * LDT + c;
    #pragma unroll
    for (int nt = 0; nt < 8; nt++) bbase[nt] = (wn + nt * 8 + q) * LDT + c;

    for (int t = 0; t < T; t++) {
        asm volatile("cp.async.wait_group 1;" ::: "memory");
        __syncthreads();

        if (t + 2 < T) load_tile(t + 2, (t + 2) % NST);
        asm volatile("cp.async.commit_group;" ::: "memory");

        const unsigned* Au = (const unsigned*)(dsm + (size_t)(t % NST) * STAGE);
        const unsigned* Bu = Au + BM * LDT;

        #pragma unroll
        for (int ks = 0; ks < 2; ks++) {        // two k16 slices per BK=32 tile
            int ko = ks * 8;
            unsigned a[4][4], b[8][2];
            #pragma unroll
            for (int mt = 0; mt < 4; mt++) {
                unsigned base = abase[mt] + ko;
                a[mt][0] = Au[base];
                a[mt][1] = Au[base + 8 * LDT];
                a[mt][2] = Au[base + 4];
                a[mt][3] = Au[base + 8 * LDT + 4];
            }
            #pragma unroll
            for (int nt = 0; nt < 8; nt++) {
                unsigned base = bbase[nt] + ko;
                b[nt][0] = Bu[base];
                b[nt][1] = Bu[base + 4];
            }
            #pragma unroll
            for (int mt = 0; mt < 4; mt++)
                #pragma unroll
                for (int nt = 0; nt < 8; nt++)
                    mma_bf16(acc[mt][nt], a[mt], b[nt]);
        }
    }

    // epilogue
    float* C = (float*)Cv;
    __nv_bfloat16* Cb = (__nv_bfloat16*)Cv;
    int cc = (lane & 3) * 2;
    #pragma unroll
    for (int mt = 0; mt < 4; mt++) {
        #pragma unroll
        for (int nt = 0; nt < 8; nt++) {
            int row = m0 + wm + mt * 16 + q;
            int col = n0 + wn + nt * 8 + cc;
            float bx = bias[col], by = bias[col + 1];
            float v0 = acc[mt][nt][0] + bx, v1 = acc[mt][nt][1] + by;
            float v2 = acc[mt][nt][2] + bx, v3 = acc[mt][nt][3] + by;
            if (EPI == 1) {
                float2 r0 = *(const float2*)&R[(size_t)row * N + col];
                float2 r1 = *(const float2*)&R[(size_t)(row + 8) * N + col];
                v0 += r0.x; v1 += r0.y; v2 += r1.x; v3 += r1.y;
            }
            if (EPI == 2) {
                v0 = 0.5f * v0 * (1.0f + erff(v0 * 0.70710678118f));
                v1 = 0.5f * v1 * (1.0f + erff(v1 * 0.70710678118f));
                v2 = 0.5f * v2 * (1.0f + erff(v2 * 0.70710678118f));
                v3 = 0.5f * v3 * (1.0f + erff(v3 * 0.70710678118f));
                *(unsigned*)&Cb[(size_t)row * N + col]       = bfpack(v0, v1);
                *(unsigned*)&Cb[(size_t)(row + 8) * N + col] = bfpack(v2, v3);
            } else {
                float2 o0 = {v0, v1}, o1 = {v2, v3};
                *(float2*)&C[(size_t)row * N + col] = o0;
                *(float2*)&C[(size_t)(row + 8) * N + col] = o1;
            }
        }
    }
}

// ---------------- causal flash attention (fp32 math, bf16 out) -------------
__global__ __launch_bounds__(128) void attn_kernel(
    const float* __restrict__ qkv, __nv_bfloat16* __restrict__ att)
{
    __shared__ float Ksm[64 * 64];
    __shared__ float Vsm[64 * 64];

    int b = blockIdx.y >> 4, h = blockIdx.y & 15;
    int q0 = blockIdx.x * 128;
    int tid = threadIdx.x;
    int gq = q0 + tid;

    const float* base = qkv + (size_t)b * 1024 * (3 * EDIM);

    float q[64], o[64];
    {
        const float4* qr = (const float4*)(base + (size_t)gq * (3 * EDIM) + h * 64);
        #pragma unroll
        for (int i = 0; i < 16; i++) {
            float4 v = qr[i];
            q[4*i] = v.x; q[4*i+1] = v.y; q[4*i+2] = v.z; q[4*i+3] = v.w;
        }
    }
    #pragma unroll
    for (int d = 0; d < 64; d++) o[d] = 0.f;
    float m = -1e30f, l = 0.f;

    int ktiles = q0 / 64 + 2;
    for (int kt = 0; kt < ktiles; kt++) {
        __syncthreads();
        #pragma unroll
        for (int i = 0; i < 8; i++) {
            int f = tid + i * 128;
            int r = f >> 4, cidx = f & 15;
            const float* krow = base + (size_t)(kt * 64 + r) * (3 * EDIM) + EDIM + h * 64;
            const float* vrow = base + (size_t)(kt * 64 + r) * (3 * EDIM) + 2 * EDIM + h * 64;
            ((float4*)Ksm)[r * 16 + cidx] = ((const float4*)krow)[cidx];
            ((float4*)Vsm)[r * 16 + cidx] = ((const float4*)vrow)[cidx];
        }
        __syncthreads();

        int smax = min(64, gq - kt * 64 + 1);
        for (int s = 0; s < smax; s++) {
            const float4* kr = (const float4*)(Ksm + s * 64);
            float dot = 0.f;
            #pragma unroll
            for (int d4 = 0; d4 < 16; d4++) {
                float4 kv = kr[d4];
                dot = fmaf(q[4*d4],   kv.x, dot);
                dot = fmaf(q[4*d4+1], kv.y, dot);
                dot = fmaf(q[4*d4+2], kv.z, dot);
                dot = fmaf(q[4*d4+3], kv.w, dot);
            }
            dot *= 0.125f;
            if (dot > m) {
                float sc = __expf(m - dot);
                l *= sc;
                #pragma unroll
                for (int d = 0; d < 64; d++) o[d] *= sc;
                m = dot;
            }
            float p = __expf(dot - m);
            l += p;
            const float4* vr = (const float4*)(Vsm + s * 64);
            #pragma unroll
            for (int d4 = 0; d4 < 16; d4++) {
                float4 vv = vr[d4];
                o[4*d4]   = fmaf(p, vv.x, o[4*d4]);
                o[4*d4+1] = fmaf(p, vv.y, o[4*d4+1]);
                o[4*d4+2] = fmaf(p, vv.z, o[4*d4+2]);
                o[4*d4+3] = fmaf(p, vv.w, o[4*d4+3]);
            }
        }
    }

    float inv = 1.0f / l;
    unsigned wbuf[32];
    #pragma unroll
    for (int i = 0; i < 32; i++)
        wbuf[i] = bfpack(o[2*i] * inv, o[2*i+1] * inv);
    uint4* dst = (uint4*)(att + (size_t)(b * 1024 + gq) * EDIM + h * 64);
    #pragma unroll
    for (int j = 0; j < 8; j++)
        dst[j] = make_uint4(wbuf[4*j], wbuf[4*j+1], wbuf[4*j+2], wbuf[4*j+3]);
}

// ---------------------------------------------------------------------------
extern "C" void kernel_launch(void* const* d_in, const int* in_sizes, int n_in,
                              void* d_out, int out_size)
{
    const float* x    = (const float*)d_in[0];
    const float* ln1w = (const float*)d_in[1];
    const float* ln1b = (const float*)d_in[2];
    const float* ln2w = (const float*)d_in[3];
    const float* ln2b = (const float*)d_in[4];
    const float* qkvw = (const float*)d_in[5];
    const float* qkvb = (const float*)d_in[6];
    const float* outw = (const float*)d_in[7];
    const float* outb = (const float*)d_in[8];
    const float* fc1w = (const float*)d_in[9];
    const float* fc1b = (const float*)d_in[10];
    const float* fc2w = (const float*)d_in[11];
    const float* fc2b = (const float*)d_in[12];
    float* out = (float*)d_out;

    __nv_bfloat16 *h, *att, *ff, *w;
    float *qkv, *x1;
    cudaGetSymbolAddress((void**)&h,   g_h);
    cudaGetSymbolAddress((void**)&qkv, g_qkv);
    cudaGetSymbolAddress((void**)&att, g_att);
    cudaGetSymbolAddress((void**)&x1,  g_x1);
    cudaGetSymbolAddress((void**)&ff,  g_ff);
    cudaGetSymbolAddress((void**)&w,   g_w);

    __nv_bfloat16* wq = w + OFF_WQKV;
    __nv_bfloat16* wo = w + OFF_WOUT;
    __nv_bfloat16* w1 = w + OFF_WFC1;
    __nv_bfloat16* w2 = w + OFF_WFC2;

    const int SMEM = 3 * (128 + 256) * 20 * 4;   // 92160 bytes
    cudaFuncSetAttribute(gemm_tc<0>, cudaFuncAttributeMaxDynamicSharedMemorySize, SMEM);
    cudaFuncSetAttribute(gemm_tc<1>, cudaFuncAttributeMaxDynamicSharedMemorySize, SMEM);
    cudaFuncSetAttribute(gemm_tc<2>, cudaFuncAttributeMaxDynamicSharedMemorySize, SMEM);

    // 0) weights -> bf16
    cvt_kernel<<<(3*1024*1024/4 + 255)/256, 256>>>((const float4*)qkvw, wq, 3*1024*1024/4);
    cvt_kernel<<<(1024*1024/4   + 255)/256, 256>>>((const float4*)outw, wo, 1024*1024/4);
    cvt_kernel<<<(4*1024*1024/4 + 255)/256, 256>>>((const float4*)fc1w, w1, 4*1024*1024/4);
    cvt_kernel<<<(4*1024*1024/4 + 255)/256, 256>>>((const float4*)fc2w, w2, 4*1024*1024/4);

    // 1) LN1 -> bf16
    ln_kernel<<<NTOK, 256>>>(x, ln1w, ln1b, h);
    // 2) QKV projection -> fp32 qkv
    gemm_tc<0><<<dim3(3*EDIM/256, NTOK/128), 256, SMEM>>>(h, wq, qkvb, nullptr, qkv, NTOK, 3*EDIM, EDIM);
    // 3) attention -> bf16 att
    attn_kernel<<<dim3(1024/128, 4*NH), 128>>>(qkv, att);
    // 4) out projection + residual(x) -> fp32 x1
    gemm_tc<1><<<dim3(EDIM/256, NTOK/128), 256, SMEM>>>(att, wo, outb, x, x1, NTOK, EDIM, EDIM);
    // 5) LN2 -> bf16
    ln_kernel<<<NTOK, 256>>>(x1, ln2w, ln2b, h);
    // 6) FC1 + GELU -> bf16 ff
    gemm_tc<2><<<dim3(FDIM/256, NTOK/128), 256, SMEM>>>(h, w1, fc1b, nullptr, ff, NTOK, FDIM, EDIM);
    // 7) FC2 + residual(x1) -> fp32 out
    gemm_tc<1><<<dim3(EDIM/256, NTOK/128), 256, SMEM>>>(ff, w2, fc2b, x1, out, NTOK, EDIM, FDIM);
}

// round 6
// speedup vs baseline: 3.2794x; 1.1585x over previous
#include <cuda_runtime.h>
#include <cuda_bf16.h>
#include <cuda_fp16.h>
#include <math.h>
#include <stdint.h>

#define EDIM 1024
#define NTOK 4096          // B*T
#define FDIM 4096
#define NH   16

// ---------------- scratch (__device__ globals; no allocs allowed) ----------
__device__ __nv_bfloat16 g_h  [NTOK * EDIM];            // LN out (bf16)
__device__ __half        g_qkv[NTOK * 3 * EDIM];        // fp16 (attn input)
__device__ __nv_bfloat16 g_att[NTOK * EDIM];            // attn out (bf16)
__device__ float         g_x1 [NTOK * EDIM];            // residual after attn
__device__ __nv_bfloat16 g_ff [(size_t)NTOK * FDIM];    // fc1-gelu out (bf16)
__device__ __nv_bfloat16 g_w  [12 * 1024 * 1024];       // bf16 weights
#define OFF_WQKV 0
#define OFF_WOUT (3*1024*1024)
#define OFF_WFC1 (4*1024*1024)
#define OFF_WFC2 (8*1024*1024)

__device__ __forceinline__ unsigned bfpack(float lo, float hi) {
    __nv_bfloat162 p = __floats2bfloat162_rn(lo, hi);
    return *(unsigned*)&p;
}
__device__ __forceinline__ unsigned hpack(float lo, float hi) {
    __half2 p = __floats2half2_rn(lo, hi);
    return *(unsigned*)&p;
}

// fast exp for x <= 0 (softmax): 2^y via exponent bits + deg-5 Taylor on frac.
// rel err ~1.7e-4. FMA/ALU pipes only (no MUFU).
__device__ __forceinline__ float fexp(float x) {
    x = fmaxf(x, -80.f);
    float y = x * 1.44269504f;
    float fl = floorf(y);
    float f = y - fl;
    float p =            1.3333558146e-3f;
    p = fmaf(p, f, 9.6181291076e-3f);
    p = fmaf(p, f, 5.5504108664e-2f);
    p = fmaf(p, f, 2.4022650696e-1f);
    p = fmaf(p, f, 6.9314718056e-1f);
    p = fmaf(p, f, 1.0f);
    int e = (int)fl;
    return p * __int_as_float((e + 127) << 23);
}

__device__ __forceinline__ void mma_bf16(float* d, const unsigned* a, const unsigned* b) {
    asm volatile(
        "mma.sync.aligned.m16n8k16.row.col.f32.bf16.bf16.f32 "
        "{%0,%1,%2,%3},{%4,%5,%6,%7},{%8,%9},{%0,%1,%2,%3};"
        : "+f"(d[0]), "+f"(d[1]), "+f"(d[2]), "+f"(d[3])
        : "r"(a[0]), "r"(a[1]), "r"(a[2]), "r"(a[3]), "r"(b[0]), "r"(b[1]));
}
__device__ __forceinline__ void mma_f16(float* d, const unsigned* a, unsigned b0, unsigned b1) {
    asm volatile(
        "mma.sync.aligned.m16n8k16.row.col.f32.f16.f16.f32 "
        "{%0,%1,%2,%3},{%4,%5,%6,%7},{%8,%9},{%0,%1,%2,%3};"
        : "+f"(d[0]), "+f"(d[1]), "+f"(d[2]), "+f"(d[3])
        : "r"(a[0]), "r"(a[1]), "r"(a[2]), "r"(a[3]), "r"(b0), "r"(b1));
}

__device__ __forceinline__ uint32_t smem_u32g(const void* p) {
    uint32_t a;
    asm("{ .reg .u64 t; cvta.to.shared.u64 t, %1; cvt.u32.u64 %0, t; }" : "=r"(a) : "l"(p));
    return a;
}

// ---------------- weight convert: fp32 -> bf16 -----------------------------
__global__ __launch_bounds__(256) void cvt_kernel(
    const float4* __restrict__ src, __nv_bfloat16* __restrict__ dst, int n4)
{
    int i = blockIdx.x * 256 + threadIdx.x;
    if (i < n4) {
        float4 v = src[i];
        uint2 o = { bfpack(v.x, v.y), bfpack(v.z, v.w) };
        ((uint2*)dst)[i] = o;
    }
}

// ---------------- LayerNorm (fp32 in, bf16 out) ----------------------------
__global__ __launch_bounds__(256) void ln_kernel(
    const float* __restrict__ x, const float* __restrict__ w,
    const float* __restrict__ b, __nv_bfloat16* __restrict__ out)
{
    __shared__ float red[2][8];
    int row = blockIdx.x;
    int tid = threadIdx.x;
    const float4* xr = (const float4*)(x + (size_t)row * EDIM);
    float4 v = xr[tid];
    float s  = v.x + v.y + v.z + v.w;
    float ss = v.x*v.x + v.y*v.y + v.z*v.z + v.w*v.w;
    #pragma unroll
    for (int o = 16; o; o >>= 1) {
        s  += __shfl_xor_sync(0xffffffffu, s,  o);
        ss += __shfl_xor_sync(0xffffffffu, ss, o);
    }
    int wid = tid >> 5, lid = tid & 31;
    if (lid == 0) { red[0][wid] = s; red[1][wid] = ss; }
    __syncthreads();
    s = 0.f; ss = 0.f;
    #pragma unroll
    for (int i = 0; i < 8; i++) { s += red[0][i]; ss += red[1][i]; }
    float mu  = s * (1.0f / EDIM);
    float var = ss * (1.0f / EDIM) - mu * mu;
    float inv = rsqrtf(var + 1e-5f);
    float4 wv = ((const float4*)w)[tid];
    float4 bv = ((const float4*)b)[tid];
    float o0 = (v.x - mu) * inv * wv.x + bv.x;
    float o1 = (v.y - mu) * inv * wv.y + bv.y;
    float o2 = (v.z - mu) * inv * wv.z + bv.z;
    float o3 = (v.w - mu) * inv * wv.w + bv.w;
    uint2 o = { bfpack(o0, o1), bfpack(o2, o3) };
    ((uint2*)(out + (size_t)row * EDIM))[tid] = o;
}

// ---------------------------------------------------------------------------
// bf16 mma.sync GEMM.  C[M,N] = A[M,K] @ Bw[N,K]^T  (row-major NT, bf16)
// Tile 128x256xBK32; warps 2x4 -> 64x64. 3-stage cp.async; fp32 accum.
// EPI: 0 = +bias -> fp32; 1 = +bias+residual -> fp32;
//      2 = +bias+GELU -> bf16; 3 = +bias -> fp16
// ---------------------------------------------------------------------------
template <int EPI>
__global__ __launch_bounds__(256, 1) void gemm_tc(
    const __nv_bfloat16* __restrict__ A, const __nv_bfloat16* __restrict__ Bw,
    const float* __restrict__ bias, const float* __restrict__ R,
    void* __restrict__ Cv, int M, int N, int K)
{
    constexpr int BM = 128, BN = 256, LDT = 20, NST = 3;  // LDT in 4-byte words
    constexpr uint32_t AOFF  = BM * LDT * 4;
    constexpr uint32_t STAGE = (BM + BN) * LDT * 4;

    extern __shared__ char dsm[];
    uint32_t sb = smem_u32g(dsm);
    int tid = threadIdx.x, warp = tid >> 5, lane = tid & 31;
    int m0 = blockIdx.y * BM, n0 = blockIdx.x * BN;
    int wm = (warp >> 2) * 64;
    int wn = (warp & 3) * 64;
    int T = K >> 5;

    float acc[4][8][4];
    #pragma unroll
    for (int i = 0; i < 4; i++)
        #pragma unroll
        for (int j = 0; j < 8; j++)
            #pragma unroll
            for (int k = 0; k < 4; k++) acc[i][j][k] = 0.f;

    auto load_tile = [&](int t, int s) {
        int k0 = t << 5;
        uint32_t base = sb + (uint32_t)s * STAGE;
        #pragma unroll
        for (int j = 0; j < 6; j++) {
            int idx = tid + j * 256;
            bool isB = idx >= 512;
            int r  = isB ? ((idx - 512) >> 2) : (idx >> 2);
            int ch = idx & 3;
            const __nv_bfloat16* g = isB ? (Bw + (size_t)(n0 + r) * K + k0 + ch * 8)
                                         : (A  + (size_t)(m0 + r) * K + k0 + ch * 8);
            uint32_t dst = base + (isB ? AOFF : 0u) + (uint32_t)(r * LDT + ch * 4) * 4u;
            asm volatile("cp.async.cg.shared.global [%0], [%1], 16;" :: "r"(dst), "l"(g));
        }
    };

    load_tile(0, 0);
    asm volatile("cp.async.commit_group;" ::: "memory");
    load_tile(1, 1);
    asm volatile("cp.async.commit_group;" ::: "memory");

    int q = lane >> 2, c = lane & 3;
    unsigned abase[4], bbase[8];
    #pragma unroll
    for (int mt = 0; mt < 4; mt++) abase[mt] = (wm + mt * 16 + q) * LDT + c;
    #pragma unroll
    for (int nt = 0; nt < 8; nt++) bbase[nt] = (wn + nt * 8 + q) * LDT + c;

    for (int t = 0; t < T; t++) {
        asm volatile("cp.async.wait_group 1;" ::: "memory");
        __syncthreads();

        if (t + 2 < T) load_tile(t + 2, (t + 2) % NST);
        asm volatile("cp.async.commit_group;" ::: "memory");

        const unsigned* Au = (const unsigned*)(dsm + (size_t)(t % NST) * STAGE);
        const unsigned* Bu = Au + BM * LDT;

        #pragma unroll
        for (int ks = 0; ks < 2; ks++) {
            int ko = ks * 8;
            unsigned a[4][4], b[8][2];
            #pragma unroll
            for (int mt = 0; mt < 4; mt++) {
                unsigned base = abase[mt] + ko;
                a[mt][0] = Au[base];
                a[mt][1] = Au[base + 8 * LDT];
                a[mt][2] = Au[base + 4];
                a[mt][3] = Au[base + 8 * LDT + 4];
            }
            #pragma unroll
            for (int nt = 0; nt < 8; nt++) {
                unsigned base = bbase[nt] + ko;
                b[nt][0] = Bu[base];
                b[nt][1] = Bu[base + 4];
            }
            #pragma unroll
            for (int mt = 0; mt < 4; mt++)
                #pragma unroll
                for (int nt = 0; nt < 8; nt++)
                    mma_bf16(acc[mt][nt], a[mt], b[nt]);
        }
    }

    // epilogue
    float* C = (float*)Cv;
    __nv_bfloat16* Cb = (__nv_bfloat16*)Cv;
    __half* Ch = (__half*)Cv;
    int cc = (lane & 3) * 2;
    #pragma unroll
    for (int mt = 0; mt < 4; mt++) {
        #pragma unroll
        for (int nt = 0; nt < 8; nt++) {
            int row = m0 + wm + mt * 16 + q;
            int col = n0 + wn + nt * 8 + cc;
            float bx = bias[col], by = bias[col + 1];
            float v0 = acc[mt][nt][0] + bx, v1 = acc[mt][nt][1] + by;
            float v2 = acc[mt][nt][2] + bx, v3 = acc[mt][nt][3] + by;
            if (EPI == 1) {
                float2 r0 = *(const float2*)&R[(size_t)row * N + col];
                float2 r1 = *(const float2*)&R[(size_t)(row + 8) * N + col];
                v0 += r0.x; v1 += r0.y; v2 += r1.x; v3 += r1.y;
            }
            if (EPI == 2) {
                v0 = 0.5f * v0 * (1.0f + erff(v0 * 0.70710678118f));
                v1 = 0.5f * v1 * (1.0f + erff(v1 * 0.70710678118f));
                v2 = 0.5f * v2 * (1.0f + erff(v2 * 0.70710678118f));
                v3 = 0.5f * v3 * (1.0f + erff(v3 * 0.70710678118f));
                *(unsigned*)&Cb[(size_t)row * N + col]       = bfpack(v0, v1);
                *(unsigned*)&Cb[(size_t)(row + 8) * N + col] = bfpack(v2, v3);
            } else if (EPI == 3) {
                *(unsigned*)&Ch[(size_t)row * N + col]       = hpack(v0, v1);
                *(unsigned*)&Ch[(size_t)(row + 8) * N + col] = hpack(v2, v3);
            } else {
                float2 o0 = {v0, v1}, o1 = {v2, v3};
                *(float2*)&C[(size_t)row * N + col] = o0;
                *(float2*)&C[(size_t)(row + 8) * N + col] = o1;
            }
        }
    }
}

// ---------------------------------------------------------------------------
// FA2 causal attention, fp16 mma, fp32 softmax (polynomial exp), bf16 out.
// Block = 64 queries of one (b,h); 4 warps, warp w handles rows w*16..w*16+15.
// K double-buffered cp.async; V prefetched to regs, transposed into smem.
// ---------------------------------------------------------------------------
#define ATP 72   // fp16 row stride (36 words): conflict-free frag LDS
__global__ __launch_bounds__(128) void attn_fa(
    const __half* __restrict__ qkv, __nv_bfloat16* __restrict__ att)
{
    __shared__ __half Qs[64 * ATP];
    __shared__ __half Ks[2][64 * ATP];
    __shared__ __half Vt[64 * ATP];

    int qt = 15 - blockIdx.x;           // heavy tiles first
    int bh = blockIdx.y;
    int b = bh >> 4, h = bh & 15;
    int tid = threadIdx.x, warp = tid >> 5, lane = tid & 31;
    int g = lane >> 2, c4 = lane & 3;

    const __half* base = qkv + (size_t)b * 1024 * 3072 + h * 64;
    uint32_t sQ = smem_u32g(Qs);
    uint32_t sK[2] = { smem_u32g(Ks[0]), smem_u32g(Ks[1]) };

    // -- async loaders: 64 rows x 128B
    auto loadQ = [&]() {
        #pragma unroll
        for (int i = 0; i < 4; i++) {
            int idx = tid + i * 128;
            int r = idx >> 3, ch = idx & 7;
            const __half* gp = base + (size_t)(qt * 64 + r) * 3072 + ch * 8;
            asm volatile("cp.async.cg.shared.global [%0], [%1], 16;"
                         :: "r"(sQ + r * (ATP * 2) + ch * 16), "l"(gp));
        }
    };
    auto loadK = [&](int kt, int buf) {
        #pragma unroll
        for (int i = 0; i < 4; i++) {
            int idx = tid + i * 128;
            int r = idx >> 3, ch = idx & 7;
            const __half* gp = base + (size_t)(kt * 64 + r) * 3072 + 1024 + ch * 8;
            asm volatile("cp.async.cg.shared.global [%0], [%1], 16;"
                         :: "r"(sK[buf] + r * (ATP * 2) + ch * 16), "l"(gp));
        }
    };

    int vr_row = tid & 63, vr_hs = tid >> 6;   // this thread stages V[vr_row][vr_hs*32..+31]
    const __half* vbase = base + 2048 + (size_t)vr_row * 3072 + vr_hs * 32;
    uint4 vr[4];

    // prologue
    loadQ();
    loadK(0, 0);
    asm volatile("cp.async.commit_group;" ::: "memory");
    #pragma unroll
    for (int i = 0; i < 4; i++) vr[i] = *(const uint4*)(vbase + i * 8);
    asm volatile("cp.async.wait_group 0;" ::: "memory");
    __syncthreads();

    // Q fragments (registers, once)
    unsigned qa[4][4];
    {
        const unsigned* Q32 = (const unsigned*)Qs;
        #pragma unroll
        for (int s = 0; s < 4; s++) {
            int r0 = (warp * 16 + g) * (ATP / 2), r1 = (warp * 16 + g + 8) * (ATP / 2);
            qa[s][0] = Q32[r0 + s * 8 + c4];
            qa[s][1] = Q32[r1 + s * 8 + c4];
            qa[s][2] = Q32[r0 + s * 8 + c4 + 4];
            qa[s][3] = Q32[r1 + s * 8 + c4 + 4];
        }
    }

    float m0 = -1e30f, m1 = -1e30f, l0 = 0.f, l1 = 0.f;
    float o[8][4];
    #pragma unroll
    for (int j = 0; j < 8; j++)
        #pragma unroll
        for (int e = 0; e < 4; e++) o[j][e] = 0.f;

    int row0 = qt * 64 + warp * 16 + g, row1 = row0 + 8;

    for (int kt = 0; kt <= qt; kt++) {
        // stage V tile kt from regs into transposed smem
        {
            const __half* vs = (const __half*)vr;
            #pragma unroll
            for (int i = 0; i < 32; i++)
                Vt[(vr_hs * 32 + i) * ATP + vr_row] = vs[i];
        }
        bool more = kt < qt;
        if (more) {
            loadK(kt + 1, (kt + 1) & 1);
            asm volatile("cp.async.commit_group;" ::: "memory");
        }
        uint4 vrN[4];
        if (more) {
            const __half* vn = vbase + (size_t)(kt + 1) * 64 * 3072;
            #pragma unroll
            for (int i = 0; i < 4; i++) vrN[i] = *(const uint4*)(vn + i * 8);
        }
        __syncthreads();   // Vt + Ks[kt&1] visible

        // S = Q @ K^T
        float s[8][4];
        #pragma unroll
        for (int j = 0; j < 8; j++)
            #pragma unroll
            for (int e = 0; e < 4; e++) s[j][e] = 0.f;
        {
            const unsigned* K32 = (const unsigned*)Ks[kt & 1];
            #pragma unroll
            for (int ks = 0; ks < 4; ks++) {
                #pragma unroll
                for (int nt = 0; nt < 8; nt++) {
                    unsigned b0 = K32[(nt * 8 + g) * (ATP / 2) + ks * 8 + c4];
                    unsigned b1 = K32[(nt * 8 + g) * (ATP / 2) + ks * 8 + c4 + 4];
                    mma_f16(s[nt], qa[ks], b0, b1);
                }
            }
        }

        // scale + causal mask
        int colb = kt * 64 + c4 * 2;
        #pragma unroll
        for (int nt = 0; nt < 8; nt++) {
            int c0 = colb + nt * 8, c1 = c0 + 1;
            s[nt][0] = (c0 <= row0) ? s[nt][0] * 0.125f : -1e30f;
            s[nt][1] = (c1 <= row0) ? s[nt][1] * 0.125f : -1e30f;
            s[nt][2] = (c0 <= row1) ? s[nt][2] * 0.125f : -1e30f;
            s[nt][3] = (c1 <= row1) ? s[nt][3] * 0.125f : -1e30f;
        }

        // online softmax
        float mx0 = -1e30f, mx1 = -1e30f;
        #pragma unroll
        for (int nt = 0; nt < 8; nt++) {
            mx0 = fmaxf(mx0, fmaxf(s[nt][0], s[nt][1]));
            mx1 = fmaxf(mx1, fmaxf(s[nt][2], s[nt][3]));
        }
        mx0 = fmaxf(mx0, __shfl_xor_sync(0xffffffffu, mx0, 1));
        mx0 = fmaxf(mx0, __shfl_xor_sync(0xffffffffu, mx0, 2));
        mx1 = fmaxf(mx1, __shfl_xor_sync(0xffffffffu, mx1, 1));
        mx1 = fmaxf(mx1, __shfl_xor_sync(0xffffffffu, mx1, 2));
        float mn0 = fmaxf(m0, mx0), mn1 = fmaxf(m1, mx1);
        float a0 = fexp(m0 - mn0), a1 = fexp(m1 - mn1);
        m0 = mn0; m1 = mn1;

        float rs0 = 0.f, rs1 = 0.f;
        unsigned pa[4][4];
        #pragma unroll
        for (int nt = 0; nt < 8; nt++) {
            float p0 = fexp(s[nt][0] - m0);
            float p1 = fexp(s[nt][1] - m0);
            float p2 = fexp(s[nt][2] - m1);
            float p3 = fexp(s[nt][3] - m1);
            rs0 += p0 + p1; rs1 += p2 + p3;
            pa[nt >> 1][(nt & 1) * 2 + 0] = hpack(p0, p1);
            pa[nt >> 1][(nt & 1) * 2 + 1] = hpack(p2, p3);
        }
        rs0 += __shfl_xor_sync(0xffffffffu, rs0, 1);
        rs0 += __shfl_xor_sync(0xffffffffu, rs0, 2);
        rs1 += __shfl_xor_sync(0xffffffffu, rs1, 1);
        rs1 += __shfl_xor_sync(0xffffffffu, rs1, 2);
        l0 = l0 * a0 + rs0;
        l1 = l1 * a1 + rs1;
        #pragma unroll
        for (int j = 0; j < 8; j++) {
            o[j][0] *= a0; o[j][1] *= a0; o[j][2] *= a1; o[j][3] *= a1;
        }

        // O += P @ V  (B-frags from transposed V)
        {
            const unsigned* V32 = (const unsigned*)Vt;
            #pragma unroll
            for (int ks = 0; ks < 4; ks++) {
                #pragma unroll
                for (int nt = 0; nt < 8; nt++) {
                    unsigned b0 = V32[(nt * 8 + g) * (ATP / 2) + ks * 8 + c4];
                    unsigned b1 = V32[(nt * 8 + g) * (ATP / 2) + ks * 8 + c4 + 4];
                    mma_f16(o[nt], pa[ks], b0, b1);
                }
            }
        }

        if (more) {
            asm volatile("cp.async.wait_group 0;" ::: "memory");
            #pragma unroll
            for (int i = 0; i < 4; i++) vr[i] = vrN[i];
        }
        __syncthreads();   // all done with Vt before next overwrite
    }

    float i0 = 1.0f / l0, i1 = 1.0f / l1;
    __nv_bfloat16* arow0 = att + (size_t)(b * 1024 + row0) * EDIM + h * 64;
    __nv_bfloat16* arow1 = att + (size_t)(b * 1024 + row1) * EDIM + h * 64;
    #pragma unroll
    for (int nt = 0; nt < 8; nt++) {
        *(unsigned*)&arow0[nt * 8 + c4 * 2] = bfpack(o[nt][0] * i0, o[nt][1] * i0);
        *(unsigned*)&arow1[nt * 8 + c4 * 2] = bfpack(o[nt][2] * i1, o[nt][3] * i1);
    }
}

// ---------------------------------------------------------------------------
extern "C" void kernel_launch(void* const* d_in, const int* in_sizes, int n_in,
                              void* d_out, int out_size)
{
    const float* x    = (const float*)d_in[0];
    const float* ln1w = (const float*)d_in[1];
    const float* ln1b = (const float*)d_in[2];
    const float* ln2w = (const float*)d_in[3];
    const float* ln2b = (const float*)d_in[4];
    const float* qkvw = (const float*)d_in[5];
    const float* qkvb = (const float*)d_in[6];
    const float* outw = (const float*)d_in[7];
    const float* outb = (const float*)d_in[8];
    const float* fc1w = (const float*)d_in[9];
    const float* fc1b = (const float*)d_in[10];
    const float* fc2w = (const float*)d_in[11];
    const float* fc2b = (const float*)d_in[12];
    float* out = (float*)d_out;

    __nv_bfloat16 *h, *att, *ff, *w;
    __half *qkv;
    float *x1;
    cudaGetSymbolAddress((void**)&h,   g_h);
    cudaGetSymbolAddress((void**)&qkv, g_qkv);
    cudaGetSymbolAddress((void**)&att, g_att);
    cudaGetSymbolAddress((void**)&x1,  g_x1);
    cudaGetSymbolAddress((void**)&ff,  g_ff);
    cudaGetSymbolAddress((void**)&w,   g_w);

    __nv_bfloat16* wq = w + OFF_WQKV;
    __nv_bfloat16* wo = w + OFF_WOUT;
    __nv_bfloat16* w1 = w + OFF_WFC1;
    __nv_bfloat16* w2 = w + OFF_WFC2;

    const int SMEM = 3 * (128 + 256) * 20 * 4;   // 92160 bytes
    cudaFuncSetAttribute(gemm_tc<1>, cudaFuncAttributeMaxDynamicSharedMemorySize, SMEM);
    cudaFuncSetAttribute(gemm_tc<2>, cudaFuncAttributeMaxDynamicSharedMemorySize, SMEM);
    cudaFuncSetAttribute(gemm_tc<3>, cudaFuncAttributeMaxDynamicSharedMemorySize, SMEM);

    // 0) weights -> bf16
    cvt_kernel<<<(3*1024*1024/4 + 255)/256, 256>>>((const float4*)qkvw, wq, 3*1024*1024/4);
    cvt_kernel<<<(1024*1024/4   + 255)/256, 256>>>((const float4*)outw, wo, 1024*1024/4);
    cvt_kernel<<<(4*1024*1024/4 + 255)/256, 256>>>((const float4*)fc1w, w1, 4*1024*1024/4);
    cvt_kernel<<<(4*1024*1024/4 + 255)/256, 256>>>((const float4*)fc2w, w2, 4*1024*1024/4);

    // 1) LN1 -> bf16
    ln_kernel<<<NTOK, 256>>>(x, ln1w, ln1b, h);
    // 2) QKV projection -> fp16 qkv
    gemm_tc<3><<<dim3(3*EDIM/256, NTOK/128), 256, SMEM>>>(h, wq, qkvb, nullptr, qkv, NTOK, 3*EDIM, EDIM);
    // 3) FA2 attention -> bf16 att
    attn_fa<<<dim3(16, 4*NH), 128>>>(qkv, att);
    // 4) out projection + residual(x) -> fp32 x1
    gemm_tc<1><<<dim3(EDIM/256, NTOK/128), 256, SMEM>>>(att, wo, outb, x, x1, NTOK, EDIM, EDIM);
    // 5) LN2 -> bf16
    ln_kernel<<<NTOK, 256>>>(x1, ln2w, ln2b, h);
    // 6) FC1 + GELU -> bf16 ff
    gemm_tc<2><<<dim3(FDIM/256, NTOK/128), 256, SMEM>>>(h, w1, fc1b, nullptr, ff, NTOK, FDIM, EDIM);
    // 7) FC2 + residual(x1) -> fp32 out
    gemm_tc<1><<<dim3(EDIM/256, NTOK/128), 256, SMEM>>>(ff, w2, fc2b, x1, out, NTOK, EDIM, FDIM);
}

// round 7
// speedup vs baseline: 5.3087x; 1.6188x over previous
#include <cuda_runtime.h>
#include <cuda_bf16.h>
#include <cuda_fp16.h>
#include <math.h>
#include <stdint.h>

#define EDIM 1024
#define NTOK 4096          // B*T
#define FDIM 4096
#define NH   16

// ---------------- scratch (__device__ globals; no allocs allowed) ----------
__device__ __nv_bfloat16 g_h  [NTOK * EDIM];            // LN out (bf16)
__device__ __half        g_qkv[NTOK * 3 * EDIM];        // fp16 (attn input)
__device__ __nv_bfloat16 g_att[NTOK * EDIM];            // attn out (bf16)
__device__ float         g_x1 [NTOK * EDIM];            // residual after attn
__device__ __nv_bfloat16 g_ff [(size_t)NTOK * FDIM];    // fc1-gelu out (bf16)
__device__ __nv_bfloat16 g_w  [12 * 1024 * 1024];       // bf16 weights
#define OFF_WQKV 0
#define OFF_WOUT (3*1024*1024)
#define OFF_WFC1 (4*1024*1024)
#define OFF_WFC2 (8*1024*1024)

__device__ __forceinline__ unsigned bfpack(float lo, float hi) {
    __nv_bfloat162 p = __floats2bfloat162_rn(lo, hi);
    return *(unsigned*)&p;
}
__device__ __forceinline__ unsigned hpack(float lo, float hi) {
    __half2 p = __floats2half2_rn(lo, hi);
    return *(unsigned*)&p;
}

// fast exp for softmax (x<=0): 2^y via exponent bits + deg-5 poly. FMA-pipe only.
__device__ __forceinline__ float fexp(float x) {
    x = fmaxf(x, -80.f);
    float y = x * 1.44269504f;
    float fl = floorf(y);
    float f = y - fl;
    float p =            1.3333558146e-3f;
    p = fmaf(p, f, 9.6181291076e-3f);
    p = fmaf(p, f, 5.5504108664e-2f);
    p = fmaf(p, f, 2.4022650696e-1f);
    p = fmaf(p, f, 6.9314718056e-1f);
    p = fmaf(p, f, 1.0f);
    int e = (int)fl;
    return p * __int_as_float((e + 127) << 23);
}

__device__ __forceinline__ void mma_bf16(float* d, const unsigned* a, const unsigned* b) {
    asm volatile(
        "mma.sync.aligned.m16n8k16.row.col.f32.bf16.bf16.f32 "
        "{%0,%1,%2,%3},{%4,%5,%6,%7},{%8,%9},{%0,%1,%2,%3};"
        : "+f"(d[0]), "+f"(d[1]), "+f"(d[2]), "+f"(d[3])
        : "r"(a[0]), "r"(a[1]), "r"(a[2]), "r"(a[3]), "r"(b[0]), "r"(b[1]));
}
__device__ __forceinline__ void mma_f16(float* d, const unsigned* a, unsigned b0, unsigned b1) {
    asm volatile(
        "mma.sync.aligned.m16n8k16.row.col.f32.f16.f16.f32 "
        "{%0,%1,%2,%3},{%4,%5,%6,%7},{%8,%9},{%0,%1,%2,%3};"
        : "+f"(d[0]), "+f"(d[1]), "+f"(d[2]), "+f"(d[3])
        : "r"(a[0]), "r"(a[1]), "r"(a[2]), "r"(a[3]), "r"(b0), "r"(b1));
}
__device__ __forceinline__ void ldsm4(unsigned& r0, unsigned& r1, unsigned& r2, unsigned& r3, uint32_t addr) {
    asm volatile("ldmatrix.sync.aligned.m8n8.x4.shared.b16 {%0,%1,%2,%3}, [%4];"
                 : "=r"(r0), "=r"(r1), "=r"(r2), "=r"(r3) : "r"(addr));
}

__device__ __forceinline__ uint32_t smem_u32g(const void* p) {
    uint32_t a;
    asm("{ .reg .u64 t; cvta.to.shared.u64 t, %1; cvt.u32.u64 %0, t; }" : "=r"(a) : "l"(p));
    return a;
}

// ---------------- weight convert: fp32 -> bf16 -----------------------------
__global__ __launch_bounds__(256) void cvt_kernel(
    const float4* __restrict__ src, __nv_bfloat16* __restrict__ dst, int n4)
{
    int i = blockIdx.x * 256 + threadIdx.x;
    if (i < n4) {
        float4 v = src[i];
        uint2 o = { bfpack(v.x, v.y), bfpack(v.z, v.w) };
        ((uint2*)dst)[i] = o;
    }
}

// ---------------- LayerNorm (fp32 in, bf16 out) ----------------------------
__global__ __launch_bounds__(256) void ln_kernel(
    const float* __restrict__ x, const float* __restrict__ w,
    const float* __restrict__ b, __nv_bfloat16* __restrict__ out)
{
    __shared__ float red[2][8];
    int row = blockIdx.x;
    int tid = threadIdx.x;
    const float4* xr = (const float4*)(x + (size_t)row * EDIM);
    float4 v = xr[tid];
    float s  = v.x + v.y + v.z + v.w;
    float ss = v.x*v.x + v.y*v.y + v.z*v.z + v.w*v.w;
    #pragma unroll
    for (int o = 16; o; o >>= 1) {
        s  += __shfl_xor_sync(0xffffffffu, s,  o);
        ss += __shfl_xor_sync(0xffffffffu, ss, o);
    }
    int wid = tid >> 5, lid = tid & 31;
    if (lid == 0) { red[0][wid] = s; red[1][wid] = ss; }
    __syncthreads();
    s = 0.f; ss = 0.f;
    #pragma unroll
    for (int i = 0; i < 8; i++) { s += red[0][i]; ss += red[1][i]; }
    float mu  = s * (1.0f / EDIM);
    float var = ss * (1.0f / EDIM) - mu * mu;
    float inv = rsqrtf(var + 1e-5f);
    float4 wv = ((const float4*)w)[tid];
    float4 bv = ((const float4*)b)[tid];
    float o0 = (v.x - mu) * inv * wv.x + bv.x;
    float o1 = (v.y - mu) * inv * wv.y + bv.y;
    float o2 = (v.z - mu) * inv * wv.z + bv.z;
    float o3 = (v.w - mu) * inv * wv.w + bv.w;
    uint2 o = { bfpack(o0, o1), bfpack(o2, o3) };
    ((uint2*)(out + (size_t)row * EDIM))[tid] = o;
}

// ---------------------------------------------------------------------------
// bf16 mma.sync GEMM with ldmatrix operand loads.
// C[M,N] = A[M,K] @ Bw[N,K]^T  (row-major NT, bf16).
// Tile 128x256xBK64; warps 2x4 -> 64x64. Rows 128B data + 16B pad (stride 144B):
// ldmatrix over 8 consecutive rows hits banks (4r..4r+3)%32 -> conflict-free.
// 3-stage cp.async; fp32 accum.
// EPI: 0 = +bias -> fp32; 1 = +bias+residual -> fp32;
//      2 = +bias+GELU -> bf16; 3 = +bias -> fp16
// ---------------------------------------------------------------------------
template <int EPI>
__global__ __launch_bounds__(256, 1) void gemm_tc(
    const __nv_bfloat16* __restrict__ A, const __nv_bfloat16* __restrict__ Bw,
    const float* __restrict__ bias, const float* __restrict__ R,
    void* __restrict__ Cv, int M, int N, int K)
{
    constexpr int BM = 128, BN = 256, NST = 3;
    constexpr uint32_t ROWB  = 144;                    // 128B data + 16B pad
    constexpr uint32_t AOFF  = BM * ROWB;
    constexpr uint32_t STAGE = (BM + BN) * ROWB;       // 55296 B

    extern __shared__ char dsm[];
    uint32_t sb = smem_u32g(dsm);
    int tid = threadIdx.x, warp = tid >> 5, lane = tid & 31;
    int m0 = blockIdx.y * BM, n0 = blockIdx.x * BN;
    int wm = (warp >> 2) * 64;
    int wn = (warp & 3) * 64;
    int T = K >> 6;

    float acc[4][8][4];
    #pragma unroll
    for (int i = 0; i < 4; i++)
        #pragma unroll
        for (int j = 0; j < 8; j++)
            #pragma unroll
            for (int k = 0; k < 4; k++) acc[i][j][k] = 0.f;

    auto load_tile = [&](int t, int s) {
        int k0 = t << 6;
        uint32_t base = sb + (uint32_t)s * STAGE;
        #pragma unroll
        for (int j = 0; j < 12; j++) {
            int idx = tid + j * 256;            // 3072 16B-chunks per stage
            bool isB = idx >= 1024;
            int r  = isB ? ((idx - 1024) >> 3) : (idx >> 3);
            int ch = idx & 7;
            const __nv_bfloat16* g = isB ? (Bw + (size_t)(n0 + r) * K + k0 + ch * 8)
                                         : (A  + (size_t)(m0 + r) * K + k0 + ch * 8);
            uint32_t dst = base + (isB ? AOFF : 0u) + (uint32_t)r * ROWB + ch * 16;
            asm volatile("cp.async.cg.shared.global [%0], [%1], 16;" :: "r"(dst), "l"(g));
        }
    };

    load_tile(0, 0);
    asm volatile("cp.async.commit_group;" ::: "memory");
    load_tile(1, 1);
    asm volatile("cp.async.commit_group;" ::: "memory");

    // ldmatrix per-thread offsets (within a stage)
    uint32_t lm   = lane & 15;
    uint32_t hi16 = ((lane >> 4) & 1) * 16;
    uint32_t aoff[4], boff[4];
    #pragma unroll
    for (int mt = 0; mt < 4; mt++) aoff[mt] = (uint32_t)(wm + mt * 16 + lm) * ROWB + hi16;
    #pragma unroll
    for (int p = 0; p < 4; p++)    boff[p]  = AOFF + (uint32_t)(wn + p * 16 + lm) * ROWB + hi16;

    for (int t = 0; t < T; t++) {
        asm volatile("cp.async.wait_group 1;" ::: "memory");
        __syncthreads();

        if (t + 2 < T) load_tile(t + 2, (t + 2) % NST);
        asm volatile("cp.async.commit_group;" ::: "memory");

        uint32_t base = sb + (uint32_t)(t % NST) * STAGE;

        #pragma unroll
        for (int ks = 0; ks < 4; ks++) {        // four k16 slices per BK=64 tile
            unsigned a[4][4], b[8][2];
            #pragma unroll
            for (int mt = 0; mt < 4; mt++)
                ldsm4(a[mt][0], a[mt][1], a[mt][2], a[mt][3], base + aoff[mt] + ks * 32);
            #pragma unroll
            for (int p = 0; p < 4; p++) {
                unsigned r0, r1, r2, r3;
                ldsm4(r0, r1, r2, r3, base + boff[p] + ks * 32);
                b[2*p][0] = r0; b[2*p+1][0] = r1; b[2*p][1] = r2; b[2*p+1][1] = r3;
            }
            #pragma unroll
            for (int mt = 0; mt < 4; mt++)
                #pragma unroll
                for (int nt = 0; nt < 8; nt++)
                    mma_bf16(acc[mt][nt], a[mt], b[nt]);
        }
    }

    // epilogue
    float* C = (float*)Cv;
    __nv_bfloat16* Cb = (__nv_bfloat16*)Cv;
    __half* Ch = (__half*)Cv;
    int q = lane >> 2;
    int cc = (lane & 3) * 2;
    #pragma unroll
    for (int mt = 0; mt < 4; mt++) {
        #pragma unroll
        for (int nt = 0; nt < 8; nt++) {
            int row = m0 + wm + mt * 16 + q;
            int col = n0 + wn + nt * 8 + cc;
            float bx = bias[col], by = bias[col + 1];
            float v0 = acc[mt][nt][0] + bx, v1 = acc[mt][nt][1] + by;
            float v2 = acc[mt][nt][2] + bx, v3 = acc[mt][nt][3] + by;
            if (EPI == 1) {
                float2 r0 = *(const float2*)&R[(size_t)row * N + col];
                float2 r1 = *(const float2*)&R[(size_t)(row + 8) * N + col];
                v0 += r0.x; v1 += r0.y; v2 += r1.x; v3 += r1.y;
            }
            if (EPI == 2) {
                v0 = 0.5f * v0 * (1.0f + erff(v0 * 0.70710678118f));
                v1 = 0.5f * v1 * (1.0f + erff(v1 * 0.70710678118f));
                v2 = 0.5f * v2 * (1.0f + erff(v2 * 0.70710678118f));
                v3 = 0.5f * v3 * (1.0f + erff(v3 * 0.70710678118f));
                *(unsigned*)&Cb[(size_t)row * N + col]       = bfpack(v0, v1);
                *(unsigned*)&Cb[(size_t)(row + 8) * N + col] = bfpack(v2, v3);
            } else if (EPI == 3) {
                *(unsigned*)&Ch[(size_t)row * N + col]       = hpack(v0, v1);
                *(unsigned*)&Ch[(size_t)(row + 8) * N + col] = hpack(v2, v3);
            } else {
                float2 o0 = {v0, v1}, o1 = {v2, v3};
                *(float2*)&C[(size_t)row * N + col] = o0;
                *(float2*)&C[(size_t)(row + 8) * N + col] = o1;
            }
        }
    }
}

// ---------------------------------------------------------------------------
// FA2 causal attention (unchanged from R6): fp16 mma, poly-exp softmax.
// ---------------------------------------------------------------------------
#define ATP 72
__global__ __launch_bounds__(128) void attn_fa(
    const __half* __restrict__ qkv, __nv_bfloat16* __restrict__ att)
{
    __shared__ __half Qs[64 * ATP];
    __shared__ __half Ks[2][64 * ATP];
    __shared__ __half Vt[64 * ATP];

    int qt = 15 - blockIdx.x;
    int bh = blockIdx.y;
    int b = bh >> 4, h = bh & 15;
    int tid = threadIdx.x, warp = tid >> 5, lane = tid & 31;
    int g = lane >> 2, c4 = lane & 3;

    const __half* base = qkv + (size_t)b * 1024 * 3072 + h * 64;
    uint32_t sQ = smem_u32g(Qs);
    uint32_t sK[2] = { smem_u32g(Ks[0]), smem_u32g(Ks[1]) };

    auto loadQ = [&]() {
        #pragma unroll
        for (int i = 0; i < 4; i++) {
            int idx = tid + i * 128;
            int r = idx >> 3, ch = idx & 7;
            const __half* gp = base + (size_t)(qt * 64 + r) * 3072 + ch * 8;
            asm volatile("cp.async.cg.shared.global [%0], [%1], 16;"
                         :: "r"(sQ + r * (ATP * 2) + ch * 16), "l"(gp));
        }
    };
    auto loadK = [&](int kt, int buf) {
        #pragma unroll
        for (int i = 0; i < 4; i++) {
            int idx = tid + i * 128;
            int r = idx >> 3, ch = idx & 7;
            const __half* gp = base + (size_t)(kt * 64 + r) * 3072 + 1024 + ch * 8;
            asm volatile("cp.async.cg.shared.global [%0], [%1], 16;"
                         :: "r"(sK[buf] + r * (ATP * 2) + ch * 16), "l"(gp));
        }
    };

    int vr_row = tid & 63, vr_hs = tid >> 6;
    const __half* vbase = base + 2048 + (size_t)vr_row * 3072 + vr_hs * 32;
    uint4 vr[4];

    loadQ();
    loadK(0, 0);
    asm volatile("cp.async.commit_group;" ::: "memory");
    #pragma unroll
    for (int i = 0; i < 4; i++) vr[i] = *(const uint4*)(vbase + i * 8);
    asm volatile("cp.async.wait_group 0;" ::: "memory");
    __syncthreads();

    unsigned qa[4][4];
    {
        const unsigned* Q32 = (const unsigned*)Qs;
        #pragma unroll
        for (int s = 0; s < 4; s++) {
            int r0 = (warp * 16 + g) * (ATP / 2), r1 = (warp * 16 + g + 8) * (ATP / 2);
            qa[s][0] = Q32[r0 + s * 8 + c4];
            qa[s][1] = Q32[r1 + s * 8 + c4];
            qa[s][2] = Q32[r0 + s * 8 + c4 + 4];
            qa[s][3] = Q32[r1 + s * 8 + c4 + 4];
        }
    }

    float m0 = -1e30f, m1 = -1e30f, l0 = 0.f, l1 = 0.f;
    float o[8][4];
    #pragma unroll
    for (int j = 0; j < 8; j++)
        #pragma unroll
        for (int e = 0; e < 4; e++) o[j][e] = 0.f;

    int row0 = qt * 64 + warp * 16 + g, row1 = row0 + 8;

    for (int kt = 0; kt <= qt; kt++) {
        {
            const __half* vs = (const __half*)vr;
            #pragma unroll
            for (int i = 0; i < 32; i++)
                Vt[(vr_hs * 32 + i) * ATP + vr_row] = vs[i];
        }
        bool more = kt < qt;
        if (more) {
            loadK(kt + 1, (kt + 1) & 1);
            asm volatile("cp.async.commit_group;" ::: "memory");
        }
        uint4 vrN[4];
        if (more) {
            const __half* vn = vbase + (size_t)(kt + 1) * 64 * 3072;
            #pragma unroll
            for (int i = 0; i < 4; i++) vrN[i] = *(const uint4*)(vn + i * 8);
        }
        __syncthreads();

        float s[8][4];
        #pragma unroll
        for (int j = 0; j < 8; j++)
            #pragma unroll
            for (int e = 0; e < 4; e++) s[j][e] = 0.f;
        {
            const unsigned* K32 = (const unsigned*)Ks[kt & 1];
            #pragma unroll
            for (int ks = 0; ks < 4; ks++) {
                #pragma unroll
                for (int nt = 0; nt < 8; nt++) {
                    unsigned b0 = K32[(nt * 8 + g) * (ATP / 2) + ks * 8 + c4];
                    unsigned b1 = K32[(nt * 8 + g) * (ATP / 2) + ks * 8 + c4 + 4];
                    mma_f16(s[nt], qa[ks], b0, b1);
                }
            }
        }

        int colb = kt * 64 + c4 * 2;
        #pragma unroll
        for (int nt = 0; nt < 8; nt++) {
            int c0 = colb + nt * 8, c1 = c0 + 1;
            s[nt][0] = (c0 <= row0) ? s[nt][0] * 0.125f : -1e30f;
            s[nt][1] = (c1 <= row0) ? s[nt][1] * 0.125f : -1e30f;
            s[nt][2] = (c0 <= row1) ? s[nt][2] * 0.125f : -1e30f;
            s[nt][3] = (c1 <= row1) ? s[nt][3] * 0.125f : -1e30f;
        }

        float mx0 = -1e30f, mx1 = -1e30f;
        #pragma unroll
        for (int nt = 0; nt < 8; nt++) {
            mx0 = fmaxf(mx0, fmaxf(s[nt][0], s[nt][1]));
            mx1 = fmaxf(mx1, fmaxf(s[nt][2], s[nt][3]));
        }
        mx0 = fmaxf(mx0, __shfl_xor_sync(0xffffffffu, mx0, 1));
        mx0 = fmaxf(mx0, __shfl_xor_sync(0xffffffffu, mx0, 2));
        mx1 = fmaxf(mx1, __shfl_xor_sync(0xffffffffu, mx1, 1));
        mx1 = fmaxf(mx1, __shfl_xor_sync(0xffffffffu, mx1, 2));
        float mn0 = fmaxf(m0, mx0), mn1 = fmaxf(m1, mx1);
        float a0 = fexp(m0 - mn0), a1 = fexp(m1 - mn1);
        m0 = mn0; m1 = mn1;

        float rs0 = 0.f, rs1 = 0.f;
        unsigned pa[4][4];
        #pragma unroll
        for (int nt = 0; nt < 8; nt++) {
            float p0 = fexp(s[nt][0] - m0);
            float p1 = fexp(s[nt][1] - m0);
            float p2 = fexp(s[nt][2] - m1);
            float p3 = fexp(s[nt][3] - m1);
            rs0 += p0 + p1; rs1 += p2 + p3;
            pa[nt >> 1][(nt & 1) * 2 + 0] = hpack(p0, p1);
            pa[nt >> 1][(nt & 1) * 2 + 1] = hpack(p2, p3);
        }
        rs0 += __shfl_xor_sync(0xffffffffu, rs0, 1);
        rs0 += __shfl_xor_sync(0xffffffffu, rs0, 2);
        rs1 += __shfl_xor_sync(0xffffffffu, rs1, 1);
        rs1 += __shfl_xor_sync(0xffffffffu, rs1, 2);
        l0 = l0 * a0 + rs0;
        l1 = l1 * a1 + rs1;
        #pragma unroll
        for (int j = 0; j < 8; j++) {
            o[j][0] *= a0; o[j][1] *= a0; o[j][2] *= a1; o[j][3] *= a1;
        }

        {
            const unsigned* V32 = (const unsigned*)Vt;
            #pragma unroll
            for (int ks = 0; ks < 4; ks++) {
                #pragma unroll
                for (int nt = 0; nt < 8; nt++) {
                    unsigned b0 = V32[(nt * 8 + g) * (ATP / 2) + ks * 8 + c4];
                    unsigned b1 = V32[(nt * 8 + g) * (ATP / 2) + ks * 8 + c4 + 4];
                    mma_f16(o[nt], pa[ks], b0, b1);
                }
            }
        }

        if (more) {
            asm volatile("cp.async.wait_group 0;" ::: "memory");
            #pragma unroll
            for (int i = 0; i < 4; i++) vr[i] = vrN[i];
        }
        __syncthreads();
    }

    float i0 = 1.0f / l0, i1 = 1.0f / l1;
    __nv_bfloat16* arow0 = att + (size_t)(b * 1024 + row0) * EDIM + h * 64;
    __nv_bfloat16* arow1 = att + (size_t)(b * 1024 + row1) * EDIM + h * 64;
    #pragma unroll
    for (int nt = 0; nt < 8; nt++) {
        *(unsigned*)&arow0[nt * 8 + c4 * 2] = bfpack(o[nt][0] * i0, o[nt][1] * i0);
        *(unsigned*)&arow1[nt * 8 + c4 * 2] = bfpack(o[nt][2] * i1, o[nt][3] * i1);
    }
}

// ---------------------------------------------------------------------------
extern "C" void kernel_launch(void* const* d_in, const int* in_sizes, int n_in,
                              void* d_out, int out_size)
{
    const float* x    = (const float*)d_in[0];
    const float* ln1w = (const float*)d_in[1];
    const float* ln1b = (const float*)d_in[2];
    const float* ln2w = (const float*)d_in[3];
    const float* ln2b = (const float*)d_in[4];
    const float* qkvw = (const float*)d_in[5];
    const float* qkvb = (const float*)d_in[6];
    const float* outw = (const float*)d_in[7];
    const float* outb = (const float*)d_in[8];
    const float* fc1w = (const float*)d_in[9];
    const float* fc1b = (const float*)d_in[10];
    const float* fc2w = (const float*)d_in[11];
    const float* fc2b = (const float*)d_in[12];
    float* out = (float*)d_out;

    __nv_bfloat16 *h, *att, *ff, *w;
    __half *qkv;
    float *x1;
    cudaGetSymbolAddress((void**)&h,   g_h);
    cudaGetSymbolAddress((void**)&qkv, g_qkv);
    cudaGetSymbolAddress((void**)&att, g_att);
    cudaGetSymbolAddress((void**)&x1,  g_x1);
    cudaGetSymbolAddress((void**)&ff,  g_ff);
    cudaGetSymbolAddress((void**)&w,   g_w);

    __nv_bfloat16* wq = w + OFF_WQKV;
    __nv_bfloat16* wo = w + OFF_WOUT;
    __nv_bfloat16* w1 = w + OFF_WFC1;
    __nv_bfloat16* w2 = w + OFF_WFC2;

    const int SMEM = 3 * (128 + 256) * 144;   // 165888 bytes
    cudaFuncSetAttribute(gemm_tc<1>, cudaFuncAttributeMaxDynamicSharedMemorySize, SMEM);
    cudaFuncSetAttribute(gemm_tc<2>, cudaFuncAttributeMaxDynamicSharedMemorySize, SMEM);
    cudaFuncSetAttribute(gemm_tc<3>, cudaFuncAttributeMaxDynamicSharedMemorySize, SMEM);

    // 0) weights -> bf16
    cvt_kernel<<<(3*1024*1024/4 + 255)/256, 256>>>((const float4*)qkvw, wq, 3*1024*1024/4);
    cvt_kernel<<<(1024*1024/4   + 255)/256, 256>>>((const float4*)outw, wo, 1024*1024/4);
    cvt_kernel<<<(4*1024*1024/4 + 255)/256, 256>>>((const float4*)fc1w, w1, 4*1024*1024/4);
    cvt_kernel<<<(4*1024*1024/4 + 255)/256, 256>>>((const float4*)fc2w, w2, 4*1024*1024/4);

    // 1) LN1 -> bf16
    ln_kernel<<<NTOK, 256>>>(x, ln1w, ln1b, h);
    // 2) QKV projection -> fp16 qkv
    gemm_tc<3><<<dim3(3*EDIM/256, NTOK/128), 256, SMEM>>>(h, wq, qkvb, nullptr, qkv, NTOK, 3*EDIM, EDIM);
    // 3) FA2 attention -> bf16 att
    attn_fa<<<dim3(16, 4*NH), 128>>>(qkv, att);
    // 4) out projection + residual(x) -> fp32 x1
    gemm_tc<1><<<dim3(EDIM/256, NTOK/128), 256, SMEM>>>(att, wo, outb, x, x1, NTOK, EDIM, EDIM);
    // 5) LN2 -> bf16
    ln_kernel<<<NTOK, 256>>>(x1, ln2w, ln2b, h);
    // 6) FC1 + GELU -> bf16 ff
    gemm_tc<2><<<dim3(FDIM/256, NTOK/128), 256, SMEM>>>(h, w1, fc1b, nullptr, ff, NTOK, FDIM, EDIM);
    // 7) FC2 + residual(x1) -> fp32 out
    gemm_tc<1><<<dim3(EDIM/256, NTOK/128), 256, SMEM>>>(ff, w2, fc2b, x1, out, NTOK, EDIM, FDIM);
}